// round 2
// baseline (speedup 1.0000x reference)
#include <cuda_runtime.h>
#include <math.h>

// Problem constants
#define T_TOK 1024
#define H_DIM 2048
#define E_NUM 32
#define I_DIM 768
#define I2    1536
#define TOPK  8
#define NGROUP 4
#define GSIZE  8    // E / NGROUP
#define TOPKG  2
#define RSCALE 2.5f

// ---------------- scratch (static device globals; no runtime allocation) ----
__device__ int   g_count[E_NUM];
__device__ int   g_offset[E_NUM];
__device__ int   g_cursor[E_NUM];
__device__ int   g_pair_token[T_TOK * TOPK];
__device__ float g_pair_w[T_TOK * TOPK];
__device__ int   g_tid_ids[T_TOK * TOPK];
__device__ float g_tid_w[T_TOK * TOPK];
__device__ float g_act[(size_t)T_TOK * TOPK * I_DIM];   // ~25 MB routed activations
__device__ float g_act_sh[(size_t)T_TOK * I_DIM];       // ~3 MB shared-expert activations

// ---------------- init: reset per-call state (graph replays!) ---------------
__global__ void init_kernel() {
    int i = threadIdx.x;
    if (i < E_NUM) { g_count[i] = 0; g_cursor[i] = 0; g_offset[i] = 0; }
}

// ---------------- routing: gate logits + grouped top-k ----------------------
__global__ void routing_kernel(const float* __restrict__ x,
                               const float* __restrict__ gw,
                               const float* __restrict__ gbias) {
    int t = blockIdx.x;
    __shared__ float xs[H_DIM];
    __shared__ float sc[E_NUM];    // sigmoid scores
    __shared__ float scc[E_NUM];   // scores + bias
    int tid = threadIdx.x;         // 256 threads
    for (int h = tid; h < H_DIM; h += 256) xs[h] = x[(size_t)t * H_DIM + h];
    __syncthreads();
    int warp = tid >> 5, lane = tid & 31;
    for (int e = warp; e < E_NUM; e += 8) {
        const float* wrow = gw + (size_t)e * H_DIM;
        float s = 0.f;
        for (int h = lane; h < H_DIM; h += 32) s += xs[h] * wrow[h];
        #pragma unroll
        for (int o = 16; o > 0; o >>= 1) s += __shfl_xor_sync(0xffffffffu, s, o);
        if (lane == 0) {
            float sg = 1.f / (1.f + expf(-s));
            sc[e] = sg;
            scc[e] = sg + gbias[e];
        }
    }
    __syncthreads();
    if (tid == 0) {
        // group score = sum of top-2 biased scores per group
        float gsc[NGROUP];
        #pragma unroll
        for (int g = 0; g < NGROUP; g++) {
            float m1 = -1e30f, m2 = -1e30f;
            for (int j = 0; j < GSIZE; j++) {
                float v = scc[g * GSIZE + j];
                if (v > m1) { m2 = m1; m1 = v; }
                else if (v > m2) { m2 = v; }
            }
            gsc[g] = m1 + m2;
        }
        // top-2 groups (ties -> lowest index, strict >)
        bool gm[NGROUP] = {false, false, false, false};
        {
            float tg[NGROUP];
            #pragma unroll
            for (int g = 0; g < NGROUP; g++) tg[g] = gsc[g];
            for (int k = 0; k < TOPKG; k++) {
                int bi = 0; float bv = tg[0];
                for (int g = 1; g < NGROUP; g++) if (tg[g] > bv) { bv = tg[g]; bi = g; }
                gm[bi] = true; tg[bi] = -1e30f;
            }
        }
        float tmp[E_NUM];
        for (int e = 0; e < E_NUM; e++) tmp[e] = gm[e / GSIZE] ? scc[e] : 0.0f;
        int ids[TOPK]; float ws[TOPK]; float wsum = 0.f;
        for (int k = 0; k < TOPK; k++) {
            int bi = 0; float bv = tmp[0];
            for (int e = 1; e < E_NUM; e++) if (tmp[e] > bv) { bv = tmp[e]; bi = e; }
            ids[k] = bi; tmp[bi] = -1e30f;
            ws[k] = sc[bi]; wsum += ws[k];
        }
        float inv = 1.f / wsum;
        for (int k = 0; k < TOPK; k++) {
            g_tid_ids[t * TOPK + k] = ids[k];
            g_tid_w[t * TOPK + k] = ws[k] * inv;
            atomicAdd(&g_count[ids[k]], 1);
        }
    }
}

// ---------------- scan: per-expert offsets --------------------------------
__global__ void scan_kernel() {
    if (threadIdx.x == 0) {
        int acc = 0;
        for (int e = 0; e < E_NUM; e++) {
            g_offset[e] = acc;
            g_cursor[e] = acc;
            acc += g_count[e];
        }
    }
}

// ---------------- fill: compact (token, weight) pairs per expert ----------
__global__ void fill_kernel() {
    int i = blockIdx.x * 256 + threadIdx.x;
    if (i >= T_TOK * TOPK) return;
    int e = g_tid_ids[i];
    int pos = atomicAdd(&g_cursor[e], 1);
    g_pair_token[pos] = i / TOPK;
    g_pair_w[pos]     = g_tid_w[i];
}

// ---------------- GEMM 1: X @ W_gate_up (+ fused SiLU*mul) ----------------
// Tiles: BM=64, BN=64 (paired with column n+I for the up half), BK=16.
// 256 threads, 4x4 register blocking, dual accumulators (gate & up).
template<bool ROUTED>
__global__ __launch_bounds__(256)
void gemm_gateup(const float* __restrict__ X, const float* __restrict__ W) {
    int e = ROUTED ? blockIdx.z : 0;
    int M = ROUTED ? g_count[e] : T_TOK;
    int m0 = blockIdx.y * 64;
    if (m0 >= M) return;
    int n0 = blockIdx.x * 64;   // n in [0, I_DIM)
    const float* B = ROUTED ? (W + (size_t)e * H_DIM * I2) : W;
    const int* rowlist = ROUTED ? (g_pair_token + g_offset[e]) : nullptr;
    float* act = ROUTED ? (g_act + (size_t)g_offset[e] * I_DIM) : g_act_sh;

    __shared__ float As[16][64];
    __shared__ float Bg[16][64];
    __shared__ float Bu[16][64];

    int tid = threadIdx.x;
    // A load mapping: 64 rows x 16 k, one float4 per thread
    int arow = tid >> 2;
    int acol = (tid & 3) * 4;
    int a_r = m0 + arow;
    int tokr;
    if (ROUTED) tokr = (a_r < M) ? rowlist[a_r] : rowlist[0];
    else        tokr = (a_r < M) ? a_r : 0;
    const float* Arow = X + (size_t)tokr * H_DIM;
    // B load mapping: 16 rows x 64 n, one float4 per thread per half
    int brow = tid >> 4;
    int bcol = (tid & 15) * 4;

    int ty = tid >> 4;   // m-quad
    int tx = tid & 15;   // n-quad
    float cg[4][4] = {};
    float cu[4][4] = {};

    for (int k0 = 0; k0 < H_DIM; k0 += 16) {
        float4 av = *(const float4*)(Arow + k0 + acol);
        As[acol + 0][arow] = av.x;
        As[acol + 1][arow] = av.y;
        As[acol + 2][arow] = av.z;
        As[acol + 3][arow] = av.w;
        const float* brow_ptr = B + (size_t)(k0 + brow) * I2 + n0 + bcol;
        *(float4*)&Bg[brow][bcol] = *(const float4*)(brow_ptr);
        *(float4*)&Bu[brow][bcol] = *(const float4*)(brow_ptr + I_DIM);
        __syncthreads();
        #pragma unroll
        for (int k = 0; k < 16; k++) {
            float a[4], bg[4], bu[4];
            *(float4*)a  = *(const float4*)&As[k][ty * 4];
            *(float4*)bg = *(const float4*)&Bg[k][tx * 4];
            *(float4*)bu = *(const float4*)&Bu[k][tx * 4];
            #pragma unroll
            for (int i = 0; i < 4; i++)
                #pragma unroll
                for (int j = 0; j < 4; j++) {
                    cg[i][j] += a[i] * bg[j];
                    cu[i][j] += a[i] * bu[j];
                }
        }
        __syncthreads();
    }

    #pragma unroll
    for (int i = 0; i < 4; i++) {
        int m = m0 + ty * 4 + i;
        if (m < M) {
            float out4[4];
            #pragma unroll
            for (int j = 0; j < 4; j++) {
                float g = cg[i][j];
                float s = g / (1.f + expf(-g));  // SiLU
                out4[j] = s * cu[i][j];
            }
            *(float4*)(act + (size_t)m * I_DIM + n0 + tx * 4) = *(float4*)out4;
        }
    }
}

// ---------------- GEMM 2: act @ W_down (+ combine epilogue) ----------------
template<bool ROUTED>
__global__ __launch_bounds__(256)
void gemm_down(const float* __restrict__ W, float* __restrict__ out) {
    int e = ROUTED ? blockIdx.z : 0;
    int M = ROUTED ? g_count[e] : T_TOK;
    int m0 = blockIdx.y * 64;
    if (m0 >= M) return;
    int n0 = blockIdx.x * 64;   // n in [0, H_DIM)
    const float* B = ROUTED ? (W + (size_t)e * I_DIM * H_DIM) : W;
    const float* A = ROUTED ? (g_act + (size_t)g_offset[e] * I_DIM) : g_act_sh;

    __shared__ float As[16][64];
    __shared__ float Bs[16][64];

    int tid = threadIdx.x;
    int arow = tid >> 2;
    int acol = (tid & 3) * 4;
    int a_r = m0 + arow;
    int a_src = (a_r < M) ? a_r : 0;
    const float* Arow = A + (size_t)a_src * I_DIM;
    int brow = tid >> 4;
    int bcol = (tid & 15) * 4;

    int ty = tid >> 4;
    int tx = tid & 15;
    float c[4][4] = {};

    for (int k0 = 0; k0 < I_DIM; k0 += 16) {
        float4 av = *(const float4*)(Arow + k0 + acol);
        As[acol + 0][arow] = av.x;
        As[acol + 1][arow] = av.y;
        As[acol + 2][arow] = av.z;
        As[acol + 3][arow] = av.w;
        *(float4*)&Bs[brow][bcol] =
            *(const float4*)(B + (size_t)(k0 + brow) * H_DIM + n0 + bcol);
        __syncthreads();
        #pragma unroll
        for (int k = 0; k < 16; k++) {
            float a[4], b[4];
            *(float4*)a = *(const float4*)&As[k][ty * 4];
            *(float4*)b = *(const float4*)&Bs[k][tx * 4];
            #pragma unroll
            for (int i = 0; i < 4; i++)
                #pragma unroll
                for (int j = 0; j < 4; j++)
                    c[i][j] += a[i] * b[j];
        }
        __syncthreads();
    }

    #pragma unroll
    for (int i = 0; i < 4; i++) {
        int m = m0 + ty * 4 + i;
        if (m < M) {
            if (ROUTED) {
                int t = g_pair_token[g_offset[e] + m];
                float w = g_pair_w[g_offset[e] + m] * RSCALE;
                float* dst = out + (size_t)t * H_DIM + n0 + tx * 4;
                #pragma unroll
                for (int j = 0; j < 4; j++) atomicAdd(dst + j, c[i][j] * w);
            } else {
                float* dst = out + (size_t)m * H_DIM + n0 + tx * 4;
                float v[4];
                #pragma unroll
                for (int j = 0; j < 4; j++) v[j] = c[i][j];
                *(float4*)dst = *(float4*)v;   // shared expert initializes out
            }
        }
    }
}

// ---------------- launch ----------------------------------------------------
extern "C" void kernel_launch(void* const* d_in, const int* in_sizes, int n_in,
                              void* d_out, int out_size) {
    (void)in_sizes; (void)n_in; (void)out_size;
    const float* hidden    = (const float*)d_in[0];  // [T, H]
    const float* gate_w    = (const float*)d_in[1];  // [E, H]
    const float* gate_bias = (const float*)d_in[2];  // [E]
    const float* w_gate_up = (const float*)d_in[3];  // [E, H, 2I]
    const float* w_down    = (const float*)d_in[4];  // [E, I, H]
    const float* s_gate_up = (const float*)d_in[5];  // [H, 2I]
    const float* s_down    = (const float*)d_in[6];  // [I, H]
    float* out = (float*)d_out;                      // [T, H]

    init_kernel<<<1, 32>>>();
    routing_kernel<<<T_TOK, 256>>>(hidden, gate_w, gate_bias);
    scan_kernel<<<1, 32>>>();
    fill_kernel<<<(T_TOK * TOPK + 255) / 256, 256>>>();

    // Shared expert (writes out = shared; runs before routed atomic-adds)
    {
        dim3 grid(I_DIM / 64, T_TOK / 64, 1);
        gemm_gateup<false><<<grid, 256>>>(hidden, s_gate_up);
    }
    {
        dim3 grid(H_DIM / 64, T_TOK / 64, 1);
        gemm_down<false><<<grid, 256>>>(s_down, out);
    }

    // Routed experts
    {
        dim3 grid(I_DIM / 64, T_TOK / 64, E_NUM);
        gemm_gateup<true><<<grid, 256>>>(hidden, w_gate_up);
    }
    {
        dim3 grid(H_DIM / 64, T_TOK / 64, E_NUM);
        gemm_down<true><<<grid, 256>>>(w_down, out);
    }
}

// round 8
// speedup vs baseline: 1.5073x; 1.5073x over previous
#include <cuda_runtime.h>
#include <math.h>
#include <stdint.h>

#define T_TOK 1024
#define H_DIM 2048
#define E_NUM 32
#define I_DIM 768
#define I2    1536
#define TOPK  8
#define NGROUP 4
#define GSIZE  8
#define TOPKG  2
#define RSCALE 2.5f

// ---------------- scratch -------------------------------------------------
__device__ int   g_count[E_NUM];
__device__ int   g_offset[E_NUM];
__device__ int   g_cursor[E_NUM];
__device__ int   g_pair_token[T_TOK * TOPK];
__device__ float g_pair_w[T_TOK * TOPK];
__device__ int   g_tid_ids[T_TOK * TOPK];
__device__ float g_tid_w[T_TOK * TOPK];
__device__ float g_act[(size_t)T_TOK * TOPK * I_DIM];   // routed activations
__device__ float g_act_sh[(size_t)T_TOK * I_DIM];       // shared-expert activations

// ---------------- helpers -------------------------------------------------
__device__ __forceinline__ uint32_t tf32hi(float v) {
    uint32_t r;
    asm("cvt.rna.tf32.f32 %0, %1;" : "=r"(r) : "f"(v));
    return r;
}
__device__ __forceinline__ void mma8(float* c,
                                     uint32_t a0, uint32_t a1, uint32_t a2, uint32_t a3,
                                     uint32_t b0, uint32_t b1) {
    asm volatile("mma.sync.aligned.m16n8k8.row.col.f32.tf32.tf32.f32 "
                 "{%0,%1,%2,%3}, {%4,%5,%6,%7}, {%8,%9}, {%0,%1,%2,%3};"
                 : "+f"(c[0]), "+f"(c[1]), "+f"(c[2]), "+f"(c[3])
                 : "r"(a0), "r"(a1), "r"(a2), "r"(a3), "r"(b0), "r"(b1));
}
__device__ __forceinline__ float silu(float x) { return x / (1.f + expf(-x)); }

// ---------------- init / routing / scan / fill (proven) ------------------
__global__ void init_kernel() {
    int i = threadIdx.x;
    if (i < E_NUM) { g_count[i] = 0; g_cursor[i] = 0; g_offset[i] = 0; }
}

__global__ void routing_kernel(const float* __restrict__ x,
                               const float* __restrict__ gw,
                               const float* __restrict__ gbias) {
    int t = blockIdx.x;
    __shared__ float xs[H_DIM];
    __shared__ float sc[E_NUM];
    __shared__ float scc[E_NUM];
    int tid = threadIdx.x;
    for (int h = tid; h < H_DIM; h += 256) xs[h] = x[(size_t)t * H_DIM + h];
    __syncthreads();
    int warp = tid >> 5, lane = tid & 31;
    for (int e = warp; e < E_NUM; e += 8) {
        const float* wrow = gw + (size_t)e * H_DIM;
        float s = 0.f;
        for (int h = lane; h < H_DIM; h += 32) s += xs[h] * wrow[h];
        #pragma unroll
        for (int o = 16; o > 0; o >>= 1) s += __shfl_xor_sync(0xffffffffu, s, o);
        if (lane == 0) {
            float sg = 1.f / (1.f + expf(-s));
            sc[e] = sg;
            scc[e] = sg + gbias[e];
        }
    }
    __syncthreads();
    if (tid == 0) {
        float gsc[NGROUP];
        #pragma unroll
        for (int g = 0; g < NGROUP; g++) {
            float m1 = -1e30f, m2 = -1e30f;
            for (int j = 0; j < GSIZE; j++) {
                float v = scc[g * GSIZE + j];
                if (v > m1) { m2 = m1; m1 = v; }
                else if (v > m2) { m2 = v; }
            }
            gsc[g] = m1 + m2;
        }
        bool gm[NGROUP] = {false, false, false, false};
        {
            float tg[NGROUP];
            #pragma unroll
            for (int g = 0; g < NGROUP; g++) tg[g] = gsc[g];
            for (int k = 0; k < TOPKG; k++) {
                int bi = 0; float bv = tg[0];
                for (int g = 1; g < NGROUP; g++) if (tg[g] > bv) { bv = tg[g]; bi = g; }
                gm[bi] = true; tg[bi] = -1e30f;
            }
        }
        float tmp[E_NUM];
        for (int e = 0; e < E_NUM; e++) tmp[e] = gm[e / GSIZE] ? scc[e] : 0.0f;
        int ids[TOPK]; float ws[TOPK]; float wsum = 0.f;
        for (int k = 0; k < TOPK; k++) {
            int bi = 0; float bv = tmp[0];
            for (int e = 1; e < E_NUM; e++) if (tmp[e] > bv) { bv = tmp[e]; bi = e; }
            ids[k] = bi; tmp[bi] = -1e30f;
            ws[k] = sc[bi]; wsum += ws[k];
        }
        float inv = 1.f / wsum;
        for (int k = 0; k < TOPK; k++) {
            g_tid_ids[t * TOPK + k] = ids[k];
            g_tid_w[t * TOPK + k] = ws[k] * inv;
            atomicAdd(&g_count[ids[k]], 1);
        }
    }
}

__global__ void scan_kernel() {
    if (threadIdx.x == 0) {
        int acc = 0;
        for (int e = 0; e < E_NUM; e++) {
            g_offset[e] = acc; g_cursor[e] = acc; acc += g_count[e];
        }
    }
}

__global__ void fill_kernel() {
    int i = blockIdx.x * 256 + threadIdx.x;
    if (i >= T_TOK * TOPK) return;
    int e = g_tid_ids[i];
    int pos = atomicAdd(&g_cursor[e], 1);
    g_pair_token[pos] = i / TOPK;
    g_pair_w[pos]     = g_tid_w[i];
}

__global__ void zero_out_kernel(float4* o) {
    int i = blockIdx.x * 256 + threadIdx.x;
    if (i < T_TOK * H_DIM / 4) o[i] = make_float4(0.f, 0.f, 0.f, 0.f);
}

// ============================================================================
// GEMM 1: X[M,2048] @ W[2048, 64(gate)+64(up)] -> act[M,768] with SiLU*mul
// BM=128, BN=64(+64 up), BK=16. 8 warps: warp tile 32x32 gate + 32x32 up.
// ============================================================================
#define LDA 20
#define LDB 17
#define G1_ASZ (128 * LDA)                 // floats
#define G1_BSZ (64 * LDB)                  // floats
#define G1_BUF (G1_ASZ + 4 * G1_BSZ)       // floats (= 6912)
#define G1_SMEM (2 * G1_BUF * 4)           // bytes (= 55296)

__global__ __launch_bounds__(256, 2)
void mma_gateup_kernel(const float* __restrict__ X,
                       const float* __restrict__ Wgu,
                       const float* __restrict__ Sgu) {
    extern __shared__ float sm[];
    const int e = blockIdx.z;
    const bool routed = (e < E_NUM);
    const int M = routed ? g_count[e] : T_TOK;
    const int m0 = blockIdx.y * 128;
    if (m0 >= M) return;
    const int n0 = blockIdx.x * 64;
    const float* W = routed ? (Wgu + (size_t)e * H_DIM * I2) : Sgu;
    const int off = routed ? g_offset[e] : 0;
    float* act = routed ? (g_act + (size_t)off * I_DIM) : g_act_sh;

    const int tid = threadIdx.x;
    const int lane = tid & 31, wid = tid >> 5;
    const int g = lane >> 2, tg = lane & 3;
    const int wm = (wid >> 1) * 32, wn = (wid & 1) * 32;

    // A fill mapping: row = tid>>1, colbase = (tid&1)*8
    const int arow_i = tid >> 1, cb = (tid & 1) * 8;
    int ar = m0 + arow_i;
    int tokr = (ar < M) ? ar : m0;
    if (routed) tokr = g_pair_token[off + tokr];
    const float* Arow = X + (size_t)tokr * H_DIM;
    // B fill mapping: n = tid&63, kbase = tid>>6; k = kbase + 4j
    const int bn = tid & 63, bk = tid >> 6;
    const float* Bgp = W + n0 + bn;
    const float* Bup = W + n0 + bn + I_DIM;

    float cg[2][4][4], cu[2][4][4];
    #pragma unroll
    for (int a = 0; a < 2; a++)
        #pragma unroll
        for (int b = 0; b < 4; b++)
            #pragma unroll
            for (int c = 0; c < 4; c++) { cg[a][b][c] = 0.f; cu[a][b][c] = 0.f; }

    float4 pa0, pa1;
    float pbg[4], pbu[4];

    const int NK = H_DIM / 16;   // 128

    // prologue load kt=0
    {
        pa0 = *(const float4*)(Arow + cb);
        pa1 = *(const float4*)(Arow + cb + 4);
        #pragma unroll
        for (int j = 0; j < 4; j++) {
            int k = bk + 4 * j;
            pbg[j] = Bgp[(size_t)k * I2];
            pbu[j] = Bup[(size_t)k * I2];
        }
    }
    // store kt=0 -> buf 0
    {
        float* As  = sm;
        float* Bgh = As + G1_ASZ;
        float* Bgl = Bgh + G1_BSZ;
        float* Buh = Bgl + G1_BSZ;
        float* Bul = Buh + G1_BSZ;
        *(float4*)&As[arow_i * LDA + cb] = pa0;
        *(float4*)&As[arow_i * LDA + cb + 4] = pa1;
        #pragma unroll
        for (int j = 0; j < 4; j++) {
            int k = bk + 4 * j;
            uint32_t h = tf32hi(pbg[j]);
            Bgh[bn * LDB + k] = __uint_as_float(h);
            Bgl[bn * LDB + k] = __uint_as_float(tf32hi(pbg[j] - __uint_as_float(h)));
            uint32_t h2 = tf32hi(pbu[j]);
            Buh[bn * LDB + k] = __uint_as_float(h2);
            Bul[bn * LDB + k] = __uint_as_float(tf32hi(pbu[j] - __uint_as_float(h2)));
        }
    }
    __syncthreads();

    for (int kt = 0; kt < NK; kt++) {
        // prefetch next tile into registers
        if (kt + 1 < NK) {
            const int k0 = (kt + 1) * 16;
            pa0 = *(const float4*)(Arow + k0 + cb);
            pa1 = *(const float4*)(Arow + k0 + cb + 4);
            #pragma unroll
            for (int j = 0; j < 4; j++) {
                int k = k0 + bk + 4 * j;
                pbg[j] = Bgp[(size_t)k * I2];
                pbu[j] = Bup[(size_t)k * I2];
            }
        }
        // compute from current buffer
        {
            const float* As  = sm + (kt & 1) * G1_BUF;
            const float* Bgh = As + G1_ASZ;
            const float* Bgl = Bgh + G1_BSZ;
            const float* Buh = Bgl + G1_BSZ;
            const float* Bul = Buh + G1_BSZ;
            #pragma unroll
            for (int ko = 0; ko < 16; ko += 8) {
                uint32_t ah[2][4], al[2][4];
                #pragma unroll
                for (int mt = 0; mt < 2; mt++) {
                    const int r0 = wm + mt * 16;
                    float a0 = As[(r0 + g) * LDA + ko + tg];
                    float a1 = As[(r0 + g + 8) * LDA + ko + tg];
                    float a2 = As[(r0 + g) * LDA + ko + tg + 4];
                    float a3 = As[(r0 + g + 8) * LDA + ko + tg + 4];
                    ah[mt][0] = tf32hi(a0); al[mt][0] = tf32hi(a0 - __uint_as_float(ah[mt][0]));
                    ah[mt][1] = tf32hi(a1); al[mt][1] = tf32hi(a1 - __uint_as_float(ah[mt][1]));
                    ah[mt][2] = tf32hi(a2); al[mt][2] = tf32hi(a2 - __uint_as_float(ah[mt][2]));
                    ah[mt][3] = tf32hi(a3); al[mt][3] = tf32hi(a3 - __uint_as_float(ah[mt][3]));
                }
                #pragma unroll
                for (int nt = 0; nt < 4; nt++) {
                    const int nr = (wn + nt * 8 + g) * LDB + ko + tg;
                    uint32_t bgh0 = __float_as_uint(Bgh[nr]);
                    uint32_t bgh1 = __float_as_uint(Bgh[nr + 4]);
                    uint32_t bgl0 = __float_as_uint(Bgl[nr]);
                    uint32_t bgl1 = __float_as_uint(Bgl[nr + 4]);
                    uint32_t buh0 = __float_as_uint(Buh[nr]);
                    uint32_t buh1 = __float_as_uint(Buh[nr + 4]);
                    uint32_t bul0 = __float_as_uint(Bul[nr]);
                    uint32_t bul1 = __float_as_uint(Bul[nr + 4]);
                    #pragma unroll
                    for (int mt = 0; mt < 2; mt++) {
                        mma8(cg[mt][nt], ah[mt][0], ah[mt][1], ah[mt][2], ah[mt][3], bgh0, bgh1);
                        mma8(cg[mt][nt], al[mt][0], al[mt][1], al[mt][2], al[mt][3], bgh0, bgh1);
                        mma8(cg[mt][nt], ah[mt][0], ah[mt][1], ah[mt][2], ah[mt][3], bgl0, bgl1);
                        mma8(cu[mt][nt], ah[mt][0], ah[mt][1], ah[mt][2], ah[mt][3], buh0, buh1);
                        mma8(cu[mt][nt], al[mt][0], al[mt][1], al[mt][2], al[mt][3], buh0, buh1);
                        mma8(cu[mt][nt], ah[mt][0], ah[mt][1], ah[mt][2], ah[mt][3], bul0, bul1);
                    }
                }
            }
        }
        __syncthreads();
        if (kt + 1 < NK) {
            float* As  = sm + ((kt + 1) & 1) * G1_BUF;
            float* Bgh = As + G1_ASZ;
            float* Bgl = Bgh + G1_BSZ;
            float* Buh = Bgl + G1_BSZ;
            float* Bul = Buh + G1_BSZ;
            *(float4*)&As[arow_i * LDA + cb] = pa0;
            *(float4*)&As[arow_i * LDA + cb + 4] = pa1;
            #pragma unroll
            for (int j = 0; j < 4; j++) {
                int k = bk + 4 * j;
                uint32_t h = tf32hi(pbg[j]);
                Bgh[bn * LDB + k] = __uint_as_float(h);
                Bgl[bn * LDB + k] = __uint_as_float(tf32hi(pbg[j] - __uint_as_float(h)));
                uint32_t h2 = tf32hi(pbu[j]);
                Buh[bn * LDB + k] = __uint_as_float(h2);
                Bul[bn * LDB + k] = __uint_as_float(tf32hi(pbu[j] - __uint_as_float(h2)));
            }
            __syncthreads();
        }
    }

    // epilogue: SiLU(gate)*up -> act
    #pragma unroll
    for (int mt = 0; mt < 2; mt++) {
        const int r1 = m0 + wm + mt * 16 + g;
        const int r2 = r1 + 8;
        #pragma unroll
        for (int nt = 0; nt < 4; nt++) {
            const int col = n0 + wn + nt * 8 + 2 * tg;
            if (r1 < M) {
                float2 o;
                o.x = silu(cg[mt][nt][0]) * cu[mt][nt][0];
                o.y = silu(cg[mt][nt][1]) * cu[mt][nt][1];
                *(float2*)(act + (size_t)(r1 - m0 + m0) * I_DIM + col) = o;
            }
            if (r2 < M) {
                float2 o;
                o.x = silu(cg[mt][nt][2]) * cu[mt][nt][2];
                o.y = silu(cg[mt][nt][3]) * cu[mt][nt][3];
                *(float2*)(act + (size_t)r2 * I_DIM + col) = o;
            }
        }
    }
}

// ============================================================================
// GEMM 2: act[M,768] @ Wd[768,2048] -> weighted atomicAdd into out[T,2048]
// BM=128, BN=128, BK=16. 8 warps: warp tile 32x64.
// ============================================================================
#define G2_ASZ (128 * LDA)
#define G2_BSZ (128 * LDB)
#define G2_BUF (G2_ASZ + 2 * G2_BSZ)       // floats (= 6912)
#define G2_SMEM (2 * G2_BUF * 4)

__global__ __launch_bounds__(256, 2)
void mma_down_kernel(const float* __restrict__ Wd,
                     const float* __restrict__ Sd,
                     float* __restrict__ out) {
    extern __shared__ float sm[];
    const int e = blockIdx.z;
    const bool routed = (e < E_NUM);
    const int M = routed ? g_count[e] : T_TOK;
    const int m0 = blockIdx.y * 128;
    if (m0 >= M) return;
    const int n0 = blockIdx.x * 128;
    const float* W = routed ? (Wd + (size_t)e * I_DIM * H_DIM) : Sd;
    const int off = routed ? g_offset[e] : 0;
    const float* A = routed ? (g_act + (size_t)off * I_DIM) : g_act_sh;

    const int tid = threadIdx.x;
    const int lane = tid & 31, wid = tid >> 5;
    const int g = lane >> 2, tg = lane & 3;
    const int wm = (wid >> 1) * 32, wn = (wid & 1) * 64;

    const int arow_i = tid >> 1, cb = (tid & 1) * 8;
    int ar = m0 + arow_i;
    const float* Arow = A + (size_t)((ar < M) ? ar : m0) * I_DIM;
    const int bn = tid & 127, bk = tid >> 7;      // bk in {0,1}
    const float* Bp = W + n0 + bn;

    float cc[2][8][4];
    #pragma unroll
    for (int a = 0; a < 2; a++)
        #pragma unroll
        for (int b = 0; b < 8; b++)
            #pragma unroll
            for (int c = 0; c < 4; c++) cc[a][b][c] = 0.f;

    float4 pa0, pa1;
    float pb[8];
    const int NK = I_DIM / 16;    // 48

    {
        pa0 = *(const float4*)(Arow + cb);
        pa1 = *(const float4*)(Arow + cb + 4);
        #pragma unroll
        for (int j = 0; j < 8; j++) {
            int k = bk + 2 * j;
            pb[j] = Bp[(size_t)k * H_DIM];
        }
    }
    {
        float* As = sm;
        float* Bh = As + G2_ASZ;
        float* Bl = Bh + G2_BSZ;
        *(float4*)&As[arow_i * LDA + cb] = pa0;
        *(float4*)&As[arow_i * LDA + cb + 4] = pa1;
        #pragma unroll
        for (int j = 0; j < 8; j++) {
            int k = bk + 2 * j;
            uint32_t h = tf32hi(pb[j]);
            Bh[bn * LDB + k] = __uint_as_float(h);
            Bl[bn * LDB + k] = __uint_as_float(tf32hi(pb[j] - __uint_as_float(h)));
        }
    }
    __syncthreads();

    for (int kt = 0; kt < NK; kt++) {
        if (kt + 1 < NK) {
            const int k0 = (kt + 1) * 16;
            pa0 = *(const float4*)(Arow + k0 + cb);
            pa1 = *(const float4*)(Arow + k0 + cb + 4);
            #pragma unroll
            for (int j = 0; j < 8; j++) {
                int k = k0 + bk + 2 * j;
                pb[j] = Bp[(size_t)k * H_DIM];
            }
        }
        {
            const float* As = sm + (kt & 1) * G2_BUF;
            const float* Bh = As + G2_ASZ;
            const float* Bl = Bh + G2_BSZ;
            #pragma unroll
            for (int ko = 0; ko < 16; ko += 8) {
                uint32_t ah[2][4], al[2][4];
                #pragma unroll
                for (int mt = 0; mt < 2; mt++) {
                    const int r0 = wm + mt * 16;
                    float a0 = As[(r0 + g) * LDA + ko + tg];
                    float a1 = As[(r0 + g + 8) * LDA + ko + tg];
                    float a2 = As[(r0 + g) * LDA + ko + tg + 4];
                    float a3 = As[(r0 + g + 8) * LDA + ko + tg + 4];
                    ah[mt][0] = tf32hi(a0); al[mt][0] = tf32hi(a0 - __uint_as_float(ah[mt][0]));
                    ah[mt][1] = tf32hi(a1); al[mt][1] = tf32hi(a1 - __uint_as_float(ah[mt][1]));
                    ah[mt][2] = tf32hi(a2); al[mt][2] = tf32hi(a2 - __uint_as_float(ah[mt][2]));
                    ah[mt][3] = tf32hi(a3); al[mt][3] = tf32hi(a3 - __uint_as_float(ah[mt][3]));
                }
                #pragma unroll
                for (int nt = 0; nt < 8; nt++) {
                    const int nr = (wn + nt * 8 + g) * LDB + ko + tg;
                    uint32_t bh0 = __float_as_uint(Bh[nr]);
                    uint32_t bh1 = __float_as_uint(Bh[nr + 4]);
                    uint32_t bl0 = __float_as_uint(Bl[nr]);
                    uint32_t bl1 = __float_as_uint(Bl[nr + 4]);
                    #pragma unroll
                    for (int mt = 0; mt < 2; mt++) {
                        mma8(cc[mt][nt], ah[mt][0], ah[mt][1], ah[mt][2], ah[mt][3], bh0, bh1);
                        mma8(cc[mt][nt], al[mt][0], al[mt][1], al[mt][2], al[mt][3], bh0, bh1);
                        mma8(cc[mt][nt], ah[mt][0], ah[mt][1], ah[mt][2], ah[mt][3], bl0, bl1);
                    }
                }
            }
        }
        __syncthreads();
        if (kt + 1 < NK) {
            float* As = sm + ((kt + 1) & 1) * G2_BUF;
            float* Bh = As + G2_ASZ;
            float* Bl = Bh + G2_BSZ;
            *(float4*)&As[arow_i * LDA + cb] = pa0;
            *(float4*)&As[arow_i * LDA + cb + 4] = pa1;
            #pragma unroll
            for (int j = 0; j < 8; j++) {
                int k = bk + 2 * j;
                uint32_t h = tf32hi(pb[j]);
                Bh[bn * LDB + k] = __uint_as_float(h);
                Bl[bn * LDB + k] = __uint_as_float(tf32hi(pb[j] - __uint_as_float(h)));
            }
            __syncthreads();
        }
    }

    // epilogue: weighted combine via atomics
    #pragma unroll
    for (int mt = 0; mt < 2; mt++) {
        const int r1 = m0 + wm + mt * 16 + g;
        const int r2 = r1 + 8;
        int tok1 = 0, tok2 = 0;
        float s1 = 0.f, s2 = 0.f;
        bool ok1 = (r1 < M), ok2 = (r2 < M);
        if (ok1) {
            if (routed) { tok1 = g_pair_token[off + r1]; s1 = g_pair_w[off + r1] * RSCALE; }
            else        { tok1 = r1; s1 = 1.0f; }
        }
        if (ok2) {
            if (routed) { tok2 = g_pair_token[off + r2]; s2 = g_pair_w[off + r2] * RSCALE; }
            else        { tok2 = r2; s2 = 1.0f; }
        }
        float* o1 = out + (size_t)tok1 * H_DIM;
        float* o2 = out + (size_t)tok2 * H_DIM;
        #pragma unroll
        for (int nt = 0; nt < 8; nt++) {
            const int col = n0 + wn + nt * 8 + 2 * tg;
            if (ok1) {
                atomicAdd(o1 + col,     cc[mt][nt][0] * s1);
                atomicAdd(o1 + col + 1, cc[mt][nt][1] * s1);
            }
            if (ok2) {
                atomicAdd(o2 + col,     cc[mt][nt][2] * s2);
                atomicAdd(o2 + col + 1, cc[mt][nt][3] * s2);
            }
        }
    }
}

// ---------------- launch ---------------------------------------------------
extern "C" void kernel_launch(void* const* d_in, const int* in_sizes, int n_in,
                              void* d_out, int out_size) {
    (void)in_sizes; (void)n_in; (void)out_size;
    const float* hidden    = (const float*)d_in[0];
    const float* gate_w    = (const float*)d_in[1];
    const float* gate_bias = (const float*)d_in[2];
    const float* w_gate_up = (const float*)d_in[3];
    const float* w_down    = (const float*)d_in[4];
    const float* s_gate_up = (const float*)d_in[5];
    const float* s_down    = (const float*)d_in[6];
    float* out = (float*)d_out;

    cudaFuncSetAttribute(mma_gateup_kernel, cudaFuncAttributeMaxDynamicSharedMemorySize, G1_SMEM);
    cudaFuncSetAttribute(mma_down_kernel,   cudaFuncAttributeMaxDynamicSharedMemorySize, G2_SMEM);

    init_kernel<<<1, 32>>>();
    routing_kernel<<<T_TOK, 256>>>(hidden, gate_w, gate_bias);
    scan_kernel<<<1, 32>>>();
    fill_kernel<<<(T_TOK * TOPK + 255) / 256, 256>>>();
    zero_out_kernel<<<(T_TOK * H_DIM / 4 + 255) / 256, 256>>>((float4*)out);

    {
        dim3 grid(I_DIM / 64, T_TOK / 128, E_NUM + 1);    // (12, 8, 33)
        mma_gateup_kernel<<<grid, 256, G1_SMEM>>>(hidden, w_gate_up, s_gate_up);
    }
    {
        dim3 grid(H_DIM / 128, T_TOK / 128, E_NUM + 1);   // (16, 8, 33)
        mma_down_kernel<<<grid, 256, G2_SMEM>>>(w_down, s_down, out);
    }
}

// round 9
// speedup vs baseline: 2.2191x; 1.4722x over previous
#include <cuda_runtime.h>
#include <math.h>
#include <stdint.h>

#define T_TOK 1024
#define H_DIM 2048
#define E_NUM 32
#define I_DIM 768
#define I2    1536
#define TOPK  8
#define NGROUP 4
#define GSIZE  8
#define TOPKG  2
#define RSCALE 2.5f

// ---------------- scratch -------------------------------------------------
__device__ int   g_count[E_NUM];
__device__ int   g_offset[E_NUM];
__device__ int   g_cursor[E_NUM];
__device__ int   g_pair_token[T_TOK * TOPK];
__device__ float g_pair_w[T_TOK * TOPK];
__device__ int   g_tid_ids[T_TOK * TOPK];
__device__ float g_tid_w[T_TOK * TOPK];
__device__ float g_act[(size_t)T_TOK * TOPK * I_DIM];   // routed activations
__device__ float g_act_sh[(size_t)T_TOK * I_DIM];       // shared-expert activations

// ---------------- helpers -------------------------------------------------
// split two fp32 into packed bf16x2 hi + bf16x2 lo (k-pair: v0 -> low half)
__device__ __forceinline__ void split2(float v0, float v1, uint32_t& h, uint32_t& l) {
    asm("cvt.rn.bf16x2.f32 %0, %1, %2;" : "=r"(h) : "f"(v1), "f"(v0));
    float h0 = __uint_as_float(h << 16);
    float h1 = __uint_as_float(h & 0xffff0000u);
    float l0 = v0 - h0;
    float l1 = v1 - h1;
    asm("cvt.rn.bf16x2.f32 %0, %1, %2;" : "=r"(l) : "f"(l1), "f"(l0));
}
__device__ __forceinline__ void mmabf(float* c,
                                      uint32_t a0, uint32_t a1, uint32_t a2, uint32_t a3,
                                      uint32_t b0, uint32_t b1) {
    asm volatile("mma.sync.aligned.m16n8k16.row.col.f32.bf16.bf16.f32 "
                 "{%0,%1,%2,%3}, {%4,%5,%6,%7}, {%8,%9}, {%0,%1,%2,%3};"
                 : "+f"(c[0]), "+f"(c[1]), "+f"(c[2]), "+f"(c[3])
                 : "r"(a0), "r"(a1), "r"(a2), "r"(a3), "r"(b0), "r"(b1));
}
__device__ __forceinline__ float silu(float x) { return x / (1.f + expf(-x)); }

// ---------------- init / routing / scan / fill (proven) ------------------
__global__ void init_kernel() {
    int i = threadIdx.x;
    if (i < E_NUM) { g_count[i] = 0; g_cursor[i] = 0; g_offset[i] = 0; }
}

__global__ void routing_kernel(const float* __restrict__ x,
                               const float* __restrict__ gw,
                               const float* __restrict__ gbias) {
    int t = blockIdx.x;
    __shared__ float xs[H_DIM];
    __shared__ float sc[E_NUM];
    __shared__ float scc[E_NUM];
    int tid = threadIdx.x;
    for (int h = tid; h < H_DIM; h += 256) xs[h] = x[(size_t)t * H_DIM + h];
    __syncthreads();
    int warp = tid >> 5, lane = tid & 31;
    for (int e = warp; e < E_NUM; e += 8) {
        const float* wrow = gw + (size_t)e * H_DIM;
        float s = 0.f;
        for (int h = lane; h < H_DIM; h += 32) s += xs[h] * wrow[h];
        #pragma unroll
        for (int o = 16; o > 0; o >>= 1) s += __shfl_xor_sync(0xffffffffu, s, o);
        if (lane == 0) {
            float sg = 1.f / (1.f + expf(-s));
            sc[e] = sg;
            scc[e] = sg + gbias[e];
        }
    }
    __syncthreads();
    if (tid == 0) {
        float gsc[NGROUP];
        #pragma unroll
        for (int g = 0; g < NGROUP; g++) {
            float m1 = -1e30f, m2 = -1e30f;
            for (int j = 0; j < GSIZE; j++) {
                float v = scc[g * GSIZE + j];
                if (v > m1) { m2 = m1; m1 = v; }
                else if (v > m2) { m2 = v; }
            }
            gsc[g] = m1 + m2;
        }
        bool gm[NGROUP] = {false, false, false, false};
        {
            float tg[NGROUP];
            #pragma unroll
            for (int g = 0; g < NGROUP; g++) tg[g] = gsc[g];
            for (int k = 0; k < TOPKG; k++) {
                int bi = 0; float bv = tg[0];
                for (int g = 1; g < NGROUP; g++) if (tg[g] > bv) { bv = tg[g]; bi = g; }
                gm[bi] = true; tg[bi] = -1e30f;
            }
        }
        float tmp[E_NUM];
        for (int e = 0; e < E_NUM; e++) tmp[e] = gm[e / GSIZE] ? scc[e] : 0.0f;
        int ids[TOPK]; float ws[TOPK]; float wsum = 0.f;
        for (int k = 0; k < TOPK; k++) {
            int bi = 0; float bv = tmp[0];
            for (int e = 1; e < E_NUM; e++) if (tmp[e] > bv) { bv = tmp[e]; bi = e; }
            ids[k] = bi; tmp[bi] = -1e30f;
            ws[k] = sc[bi]; wsum += ws[k];
        }
        float inv = 1.f / wsum;
        for (int k = 0; k < TOPK; k++) {
            g_tid_ids[t * TOPK + k] = ids[k];
            g_tid_w[t * TOPK + k] = ws[k] * inv;
            atomicAdd(&g_count[ids[k]], 1);
        }
    }
}

__global__ void scan_kernel() {
    if (threadIdx.x == 0) {
        int acc = 0;
        for (int e = 0; e < E_NUM; e++) {
            g_offset[e] = acc; g_cursor[e] = acc; acc += g_count[e];
        }
    }
}

__global__ void fill_kernel() {
    int i = blockIdx.x * 256 + threadIdx.x;
    if (i >= T_TOK * TOPK) return;
    int e = g_tid_ids[i];
    int pos = atomicAdd(&g_cursor[e], 1);
    g_pair_token[pos] = i / TOPK;
    g_pair_w[pos]     = g_tid_w[i];
}

__global__ void zero_out_kernel(float4* o) {
    int i = blockIdx.x * 256 + threadIdx.x;
    if (i < T_TOK * H_DIM / 4) o[i] = make_float4(0.f, 0.f, 0.f, 0.f);
}

// ============================================================================
// GEMM 1 (bf16 3-term): X[M,2048] @ W[2048, 64(gate)+64(up)] -> act, SiLU*mul
// BM=128, BN=64(+64 up), BK=16 (one m16n8k16 slab per buffer).
// SMEM uint layout per buffer: A_hi[128*12], A_lo, Bgh[64*12], Bgl, Buh, Bul
// ============================================================================
#define SA 12
#define G1_A  (128 * SA)                  // uints per A matrix
#define G1_B  (64 * SA)                   // uints per B matrix
#define G1_BUF (2 * G1_A + 4 * G1_B)      // uints per buffer = 6144
#define G1_SMEM (2 * G1_BUF * 4)          // bytes = 49152

__global__ __launch_bounds__(256, 2)
void mma_gateup_kernel(const float* __restrict__ X,
                       const float* __restrict__ Wgu,
                       const float* __restrict__ Sgu) {
    extern __shared__ uint32_t smu[];
    const int e = blockIdx.z;
    const bool routed = (e < E_NUM);
    const int M = routed ? g_count[e] : T_TOK;
    const int m0 = blockIdx.y * 128;
    if (m0 >= M) return;
    const int n0 = blockIdx.x * 64;
    const float* W = routed ? (Wgu + (size_t)e * H_DIM * I2) : Sgu;
    const int off = routed ? g_offset[e] : 0;
    float* act = routed ? (g_act + (size_t)off * I_DIM) : g_act_sh;

    const int tid = threadIdx.x;
    const int lane = tid & 31, wid = tid >> 5;
    const int g = lane >> 2, tg = lane & 3;
    const int wm = (wid >> 1) * 32, wn = (wid & 1) * 32;

    // A fill: row = tid>>1, k-base cb = (tid&1)*8
    const int arow_i = tid >> 1, cb = (tid & 1) * 8;
    int ar = m0 + arow_i;
    int tokr = (ar < M) ? ar : m0;
    if (routed) tokr = g_pair_token[off + tokr];
    const float* Arow = X + (size_t)tokr * H_DIM;
    // B fill: n = tid&63, kpair-base bkp = tid>>6 -> kpairs {bkp, bkp+4}
    const int bn = tid & 63, bkp = tid >> 6;
    const float* Bgp = W + n0 + bn;
    const float* Bup = W + n0 + bn + I_DIM;

    float cg[2][4][4], cu[2][4][4];
    #pragma unroll
    for (int a = 0; a < 2; a++)
        #pragma unroll
        for (int b = 0; b < 4; b++)
            #pragma unroll
            for (int c = 0; c < 4; c++) { cg[a][b][c] = 0.f; cu[a][b][c] = 0.f; }

    float4 pa0, pa1;
    float pg[4], pu[4];
    const int NK = H_DIM / 16;   // 128

    // prologue load kt=0
    pa0 = *(const float4*)(Arow + cb);
    pa1 = *(const float4*)(Arow + cb + 4);
    pg[0] = Bgp[(size_t)(2 * bkp) * I2];     pg[1] = Bgp[(size_t)(2 * bkp + 1) * I2];
    pg[2] = Bgp[(size_t)(2 * bkp + 8) * I2]; pg[3] = Bgp[(size_t)(2 * bkp + 9) * I2];
    pu[0] = Bup[(size_t)(2 * bkp) * I2];     pu[1] = Bup[(size_t)(2 * bkp + 1) * I2];
    pu[2] = Bup[(size_t)(2 * bkp + 8) * I2]; pu[3] = Bup[(size_t)(2 * bkp + 9) * I2];

    {
        uint32_t* Ah = smu;
        uint32_t* Al = Ah + G1_A;
        uint32_t* Bgh = Al + G1_A;
        uint32_t* Bgl = Bgh + G1_B;
        uint32_t* Buh = Bgl + G1_B;
        uint32_t* Bul = Buh + G1_B;
        uint32_t h, l;
        int abase = arow_i * SA + cb / 2;
        split2(pa0.x, pa0.y, h, l); Ah[abase + 0] = h; Al[abase + 0] = l;
        split2(pa0.z, pa0.w, h, l); Ah[abase + 1] = h; Al[abase + 1] = l;
        split2(pa1.x, pa1.y, h, l); Ah[abase + 2] = h; Al[abase + 2] = l;
        split2(pa1.z, pa1.w, h, l); Ah[abase + 3] = h; Al[abase + 3] = l;
        int bbase = bn * SA + bkp;
        split2(pg[0], pg[1], h, l); Bgh[bbase] = h;     Bgl[bbase] = l;
        split2(pg[2], pg[3], h, l); Bgh[bbase + 4] = h; Bgl[bbase + 4] = l;
        split2(pu[0], pu[1], h, l); Buh[bbase] = h;     Bul[bbase] = l;
        split2(pu[2], pu[3], h, l); Buh[bbase + 4] = h; Bul[bbase + 4] = l;
    }
    __syncthreads();

    for (int kt = 0; kt < NK; kt++) {
        if (kt + 1 < NK) {
            const int k0 = (kt + 1) * 16;
            pa0 = *(const float4*)(Arow + k0 + cb);
            pa1 = *(const float4*)(Arow + k0 + cb + 4);
            pg[0] = Bgp[(size_t)(k0 + 2 * bkp) * I2];     pg[1] = Bgp[(size_t)(k0 + 2 * bkp + 1) * I2];
            pg[2] = Bgp[(size_t)(k0 + 2 * bkp + 8) * I2]; pg[3] = Bgp[(size_t)(k0 + 2 * bkp + 9) * I2];
            pu[0] = Bup[(size_t)(k0 + 2 * bkp) * I2];     pu[1] = Bup[(size_t)(k0 + 2 * bkp + 1) * I2];
            pu[2] = Bup[(size_t)(k0 + 2 * bkp + 8) * I2]; pu[3] = Bup[(size_t)(k0 + 2 * bkp + 9) * I2];
        }
        {
            const uint32_t* Ah = smu + (kt & 1) * G1_BUF;
            const uint32_t* Al = Ah + G1_A;
            const uint32_t* Bgh = Al + G1_A;
            const uint32_t* Bgl = Bgh + G1_B;
            const uint32_t* Buh = Bgl + G1_B;
            const uint32_t* Bul = Buh + G1_B;
            uint32_t ah[2][4], al[2][4];
            #pragma unroll
            for (int mt = 0; mt < 2; mt++) {
                const int r0 = wm + mt * 16;
                const int i0 = (r0 + g) * SA;
                const int i1 = (r0 + g + 8) * SA;
                ah[mt][0] = Ah[i0 + tg];     ah[mt][1] = Ah[i1 + tg];
                ah[mt][2] = Ah[i0 + tg + 4]; ah[mt][3] = Ah[i1 + tg + 4];
                al[mt][0] = Al[i0 + tg];     al[mt][1] = Al[i1 + tg];
                al[mt][2] = Al[i0 + tg + 4]; al[mt][3] = Al[i1 + tg + 4];
            }
            #pragma unroll
            for (int nt = 0; nt < 4; nt++) {
                const int nb = (wn + nt * 8 + g) * SA;
                uint32_t bgh0 = Bgh[nb + tg], bgh1 = Bgh[nb + tg + 4];
                uint32_t bgl0 = Bgl[nb + tg], bgl1 = Bgl[nb + tg + 4];
                uint32_t buh0 = Buh[nb + tg], buh1 = Buh[nb + tg + 4];
                uint32_t bul0 = Bul[nb + tg], bul1 = Bul[nb + tg + 4];
                #pragma unroll
                for (int mt = 0; mt < 2; mt++) {
                    mmabf(cg[mt][nt], ah[mt][0], ah[mt][1], ah[mt][2], ah[mt][3], bgh0, bgh1);
                    mmabf(cg[mt][nt], al[mt][0], al[mt][1], al[mt][2], al[mt][3], bgh0, bgh1);
                    mmabf(cg[mt][nt], ah[mt][0], ah[mt][1], ah[mt][2], ah[mt][3], bgl0, bgl1);
                    mmabf(cu[mt][nt], ah[mt][0], ah[mt][1], ah[mt][2], ah[mt][3], buh0, buh1);
                    mmabf(cu[mt][nt], al[mt][0], al[mt][1], al[mt][2], al[mt][3], buh0, buh1);
                    mmabf(cu[mt][nt], ah[mt][0], ah[mt][1], ah[mt][2], ah[mt][3], bul0, bul1);
                }
            }
        }
        __syncthreads();
        if (kt + 1 < NK) {
            uint32_t* Ah = smu + ((kt + 1) & 1) * G1_BUF;
            uint32_t* Al = Ah + G1_A;
            uint32_t* Bgh = Al + G1_A;
            uint32_t* Bgl = Bgh + G1_B;
            uint32_t* Buh = Bgl + G1_B;
            uint32_t* Bul = Buh + G1_B;
            uint32_t h, l;
            int abase = arow_i * SA + cb / 2;
            split2(pa0.x, pa0.y, h, l); Ah[abase + 0] = h; Al[abase + 0] = l;
            split2(pa0.z, pa0.w, h, l); Ah[abase + 1] = h; Al[abase + 1] = l;
            split2(pa1.x, pa1.y, h, l); Ah[abase + 2] = h; Al[abase + 2] = l;
            split2(pa1.z, pa1.w, h, l); Ah[abase + 3] = h; Al[abase + 3] = l;
            int bbase = bn * SA + bkp;
            split2(pg[0], pg[1], h, l); Bgh[bbase] = h;     Bgl[bbase] = l;
            split2(pg[2], pg[3], h, l); Bgh[bbase + 4] = h; Bgl[bbase + 4] = l;
            split2(pu[0], pu[1], h, l); Buh[bbase] = h;     Bul[bbase] = l;
            split2(pu[2], pu[3], h, l); Buh[bbase + 4] = h; Bul[bbase + 4] = l;
            __syncthreads();
        }
    }

    // epilogue: SiLU(gate)*up -> act
    #pragma unroll
    for (int mt = 0; mt < 2; mt++) {
        const int r1 = m0 + wm + mt * 16 + g;
        const int r2 = r1 + 8;
        #pragma unroll
        for (int nt = 0; nt < 4; nt++) {
            const int col = n0 + wn + nt * 8 + 2 * tg;
            if (r1 < M) {
                float2 o;
                o.x = silu(cg[mt][nt][0]) * cu[mt][nt][0];
                o.y = silu(cg[mt][nt][1]) * cu[mt][nt][1];
                *(float2*)(act + (size_t)r1 * I_DIM + col) = o;
            }
            if (r2 < M) {
                float2 o;
                o.x = silu(cg[mt][nt][2]) * cu[mt][nt][2];
                o.y = silu(cg[mt][nt][3]) * cu[mt][nt][3];
                *(float2*)(act + (size_t)r2 * I_DIM + col) = o;
            }
        }
    }
}

// ============================================================================
// GEMM 2 (bf16 3-term): act[M,768] @ Wd[768,2048] -> weighted atomicAdd out
// BM=128, BN=128, BK=16. 8 warps: warp tile 32x64.
// ============================================================================
#define G2_A  (128 * SA)
#define G2_B  (128 * SA)
#define G2_BUF (2 * G2_A + 2 * G2_B)      // uints = 6144
#define G2_SMEM (2 * G2_BUF * 4)          // 49152

__global__ __launch_bounds__(256, 2)
void mma_down_kernel(const float* __restrict__ Wd,
                     const float* __restrict__ Sd,
                     float* __restrict__ out) {
    extern __shared__ uint32_t smu[];
    const int e = blockIdx.z;
    const bool routed = (e < E_NUM);
    const int M = routed ? g_count[e] : T_TOK;
    const int m0 = blockIdx.y * 128;
    if (m0 >= M) return;
    const int n0 = blockIdx.x * 128;
    const float* W = routed ? (Wd + (size_t)e * I_DIM * H_DIM) : Sd;
    const int off = routed ? g_offset[e] : 0;
    const float* A = routed ? (g_act + (size_t)off * I_DIM) : g_act_sh;

    const int tid = threadIdx.x;
    const int lane = tid & 31, wid = tid >> 5;
    const int g = lane >> 2, tg = lane & 3;
    const int wm = (wid >> 1) * 32, wn = (wid & 1) * 64;

    const int arow_i = tid >> 1, cb = (tid & 1) * 8;
    int ar = m0 + arow_i;
    const float* Arow = A + (size_t)((ar < M) ? ar : m0) * I_DIM;
    const int bn = tid & 127, bkp = tid >> 7;     // bkp in {0,1} -> kpairs {bkp, bkp+2, bkp+4, bkp+6}
    const float* Bp = W + n0 + bn;

    float cc[2][8][4];
    #pragma unroll
    for (int a = 0; a < 2; a++)
        #pragma unroll
        for (int b = 0; b < 8; b++)
            #pragma unroll
            for (int c = 0; c < 4; c++) cc[a][b][c] = 0.f;

    float4 pa0, pa1;
    float pb[8];
    const int NK = I_DIM / 16;    // 48

    pa0 = *(const float4*)(Arow + cb);
    pa1 = *(const float4*)(Arow + cb + 4);
    #pragma unroll
    for (int j = 0; j < 4; j++) {
        int kp = bkp + 2 * j;
        pb[2 * j]     = Bp[(size_t)(2 * kp) * H_DIM];
        pb[2 * j + 1] = Bp[(size_t)(2 * kp + 1) * H_DIM];
    }
    {
        uint32_t* Ah = smu;
        uint32_t* Al = Ah + G2_A;
        uint32_t* Bh = Al + G2_A;
        uint32_t* Bl = Bh + G2_B;
        uint32_t h, l;
        int abase = arow_i * SA + cb / 2;
        split2(pa0.x, pa0.y, h, l); Ah[abase + 0] = h; Al[abase + 0] = l;
        split2(pa0.z, pa0.w, h, l); Ah[abase + 1] = h; Al[abase + 1] = l;
        split2(pa1.x, pa1.y, h, l); Ah[abase + 2] = h; Al[abase + 2] = l;
        split2(pa1.z, pa1.w, h, l); Ah[abase + 3] = h; Al[abase + 3] = l;
        #pragma unroll
        for (int j = 0; j < 4; j++) {
            int kp = bkp + 2 * j;
            split2(pb[2 * j], pb[2 * j + 1], h, l);
            Bh[bn * SA + kp] = h; Bl[bn * SA + kp] = l;
        }
    }
    __syncthreads();

    for (int kt = 0; kt < NK; kt++) {
        if (kt + 1 < NK) {
            const int k0 = (kt + 1) * 16;
            pa0 = *(const float4*)(Arow + k0 + cb);
            pa1 = *(const float4*)(Arow + k0 + cb + 4);
            #pragma unroll
            for (int j = 0; j < 4; j++) {
                int kp = bkp + 2 * j;
                pb[2 * j]     = Bp[(size_t)(k0 + 2 * kp) * H_DIM];
                pb[2 * j + 1] = Bp[(size_t)(k0 + 2 * kp + 1) * H_DIM];
            }
        }
        {
            const uint32_t* Ah = smu + (kt & 1) * G2_BUF;
            const uint32_t* Al = Ah + G2_A;
            const uint32_t* Bh = Al + G2_A;
            const uint32_t* Bl = Bh + G2_B;
            uint32_t ah[2][4], al[2][4];
            #pragma unroll
            for (int mt = 0; mt < 2; mt++) {
                const int r0 = wm + mt * 16;
                const int i0 = (r0 + g) * SA;
                const int i1 = (r0 + g + 8) * SA;
                ah[mt][0] = Ah[i0 + tg];     ah[mt][1] = Ah[i1 + tg];
                ah[mt][2] = Ah[i0 + tg + 4]; ah[mt][3] = Ah[i1 + tg + 4];
                al[mt][0] = Al[i0 + tg];     al[mt][1] = Al[i1 + tg];
                al[mt][2] = Al[i0 + tg + 4]; al[mt][3] = Al[i1 + tg + 4];
            }
            #pragma unroll
            for (int nt = 0; nt < 8; nt++) {
                const int nb = (wn + nt * 8 + g) * SA;
                uint32_t bh0 = Bh[nb + tg], bh1 = Bh[nb + tg + 4];
                uint32_t bl0 = Bl[nb + tg], bl1 = Bl[nb + tg + 4];
                #pragma unroll
                for (int mt = 0; mt < 2; mt++) {
                    mmabf(cc[mt][nt], ah[mt][0], ah[mt][1], ah[mt][2], ah[mt][3], bh0, bh1);
                    mmabf(cc[mt][nt], al[mt][0], al[mt][1], al[mt][2], al[mt][3], bh0, bh1);
                    mmabf(cc[mt][nt], ah[mt][0], ah[mt][1], ah[mt][2], ah[mt][3], bl0, bl1);
                }
            }
        }
        __syncthreads();
        if (kt + 1 < NK) {
            uint32_t* Ah = smu + ((kt + 1) & 1) * G2_BUF;
            uint32_t* Al = Ah + G2_A;
            uint32_t* Bh = Al + G2_A;
            uint32_t* Bl = Bh + G2_B;
            uint32_t h, l;
            int abase = arow_i * SA + cb / 2;
            split2(pa0.x, pa0.y, h, l); Ah[abase + 0] = h; Al[abase + 0] = l;
            split2(pa0.z, pa0.w, h, l); Ah[abase + 1] = h; Al[abase + 1] = l;
            split2(pa1.x, pa1.y, h, l); Ah[abase + 2] = h; Al[abase + 2] = l;
            split2(pa1.z, pa1.w, h, l); Ah[abase + 3] = h; Al[abase + 3] = l;
            #pragma unroll
            for (int j = 0; j < 4; j++) {
                int kp = bkp + 2 * j;
                split2(pb[2 * j], pb[2 * j + 1], h, l);
                Bh[bn * SA + kp] = h; Bl[bn * SA + kp] = l;
            }
            __syncthreads();
        }
    }

    // epilogue: weighted combine via atomics
    #pragma unroll
    for (int mt = 0; mt < 2; mt++) {
        const int r1 = m0 + wm + mt * 16 + g;
        const int r2 = r1 + 8;
        int tok1 = 0, tok2 = 0;
        float s1 = 0.f, s2 = 0.f;
        bool ok1 = (r1 < M), ok2 = (r2 < M);
        if (ok1) {
            if (routed) { tok1 = g_pair_token[off + r1]; s1 = g_pair_w[off + r1] * RSCALE; }
            else        { tok1 = r1; s1 = 1.0f; }
        }
        if (ok2) {
            if (routed) { tok2 = g_pair_token[off + r2]; s2 = g_pair_w[off + r2] * RSCALE; }
            else        { tok2 = r2; s2 = 1.0f; }
        }
        float* o1 = out + (size_t)tok1 * H_DIM;
        float* o2 = out + (size_t)tok2 * H_DIM;
        #pragma unroll
        for (int nt = 0; nt < 8; nt++) {
            const int col = n0 + wn + nt * 8 + 2 * tg;
            if (ok1) {
                atomicAdd(o1 + col,     cc[mt][nt][0] * s1);
                atomicAdd(o1 + col + 1, cc[mt][nt][1] * s1);
            }
            if (ok2) {
                atomicAdd(o2 + col,     cc[mt][nt][2] * s2);
                atomicAdd(o2 + col + 1, cc[mt][nt][3] * s2);
            }
        }
    }
}

// ---------------- launch ---------------------------------------------------
extern "C" void kernel_launch(void* const* d_in, const int* in_sizes, int n_in,
                              void* d_out, int out_size) {
    (void)in_sizes; (void)n_in; (void)out_size;
    const float* hidden    = (const float*)d_in[0];
    const float* gate_w    = (const float*)d_in[1];
    const float* gate_bias = (const float*)d_in[2];
    const float* w_gate_up = (const float*)d_in[3];
    const float* w_down    = (const float*)d_in[4];
    const float* s_gate_up = (const float*)d_in[5];
    const float* s_down    = (const float*)d_in[6];
    float* out = (float*)d_out;

    cudaFuncSetAttribute(mma_gateup_kernel, cudaFuncAttributeMaxDynamicSharedMemorySize, G1_SMEM);
    cudaFuncSetAttribute(mma_down_kernel,   cudaFuncAttributeMaxDynamicSharedMemorySize, G2_SMEM);

    init_kernel<<<1, 32>>>();
    routing_kernel<<<T_TOK, 256>>>(hidden, gate_w, gate_bias);
    scan_kernel<<<1, 32>>>();
    fill_kernel<<<(T_TOK * TOPK + 255) / 256, 256>>>();
    zero_out_kernel<<<(T_TOK * H_DIM / 4 + 255) / 256, 256>>>((float4*)out);

    {
        dim3 grid(I_DIM / 64, T_TOK / 128, E_NUM + 1);    // (12, 8, 33)
        mma_gateup_kernel<<<grid, 256, G1_SMEM>>>(hidden, w_gate_up, s_gate_up);
    }
    {
        dim3 grid(H_DIM / 128, T_TOK / 128, E_NUM + 1);   // (16, 8, 33)
        mma_down_kernel<<<grid, 256, G2_SMEM>>>(w_down, s_down, out);
    }
}

// round 10
// speedup vs baseline: 2.9271x; 1.3191x over previous
#include <cuda_runtime.h>
#include <cuda_fp16.h>
#include <math.h>
#include <stdint.h>

#define T_TOK 1024
#define H_DIM 2048
#define E_NUM 32
#define I_DIM 768
#define I2    1536
#define TOPK  8
#define NGROUP 4
#define GSIZE  8
#define TOPKG  2
#define RSCALE 2.5f

// ---------------- scratch -------------------------------------------------
__device__ int   g_count[E_NUM];
__device__ int   g_offset[E_NUM];
__device__ int   g_cursor[E_NUM];
__device__ int   g_pair_token[T_TOK * TOPK];
__device__ float g_pair_w[T_TOK * TOPK];
__device__ int   g_tid_ids[T_TOK * TOPK];
__device__ float g_tid_w[T_TOK * TOPK];
__device__ float g_act[(size_t)T_TOK * TOPK * I_DIM];   // routed activations
__device__ float g_act_sh[(size_t)T_TOK * I_DIM];       // shared-expert activations

// ---------------- helpers -------------------------------------------------
// split two fp32 into packed fp16x2 hi + fp16x2 lo (k-pair: v0 -> low half)
__device__ __forceinline__ void split2h(float v0, float v1, uint32_t& h, uint32_t& l) {
    asm("cvt.rn.f16x2.f32 %0, %1, %2;" : "=r"(h) : "f"(v1), "f"(v0));
    __half2 h2 = *reinterpret_cast<__half2*>(&h);
    float h0 = __half2float(__low2half(h2));
    float h1 = __half2float(__high2half(h2));
    asm("cvt.rn.f16x2.f32 %0, %1, %2;" : "=r"(l) : "f"(v1 - h1), "f"(v0 - h0));
}
__device__ __forceinline__ uint32_t pack2h(float v0, float v1) {
    uint32_t r;
    asm("cvt.rn.f16x2.f32 %0, %1, %2;" : "=r"(r) : "f"(v1), "f"(v0));
    return r;
}
__device__ __forceinline__ void mmah(float* c,
                                     uint32_t a0, uint32_t a1, uint32_t a2, uint32_t a3,
                                     uint32_t b0, uint32_t b1) {
    asm volatile("mma.sync.aligned.m16n8k16.row.col.f32.f16.f16.f32 "
                 "{%0,%1,%2,%3}, {%4,%5,%6,%7}, {%8,%9}, {%0,%1,%2,%3};"
                 : "+f"(c[0]), "+f"(c[1]), "+f"(c[2]), "+f"(c[3])
                 : "r"(a0), "r"(a1), "r"(a2), "r"(a3), "r"(b0), "r"(b1));
}
__device__ __forceinline__ float silu(float x) { return x / (1.f + expf(-x)); }

// ---------------- init / routing / scan / fill (proven) ------------------
__global__ void init_kernel() {
    int i = threadIdx.x;
    if (i < E_NUM) { g_count[i] = 0; g_cursor[i] = 0; g_offset[i] = 0; }
}

__global__ void routing_kernel(const float* __restrict__ x,
                               const float* __restrict__ gw,
                               const float* __restrict__ gbias) {
    int t = blockIdx.x;
    __shared__ float xs[H_DIM];
    __shared__ float sc[E_NUM];
    __shared__ float scc[E_NUM];
    int tid = threadIdx.x;
    for (int h = tid; h < H_DIM; h += 256) xs[h] = x[(size_t)t * H_DIM + h];
    __syncthreads();
    int warp = tid >> 5, lane = tid & 31;
    for (int e = warp; e < E_NUM; e += 8) {
        const float* wrow = gw + (size_t)e * H_DIM;
        float s = 0.f;
        for (int h = lane; h < H_DIM; h += 32) s += xs[h] * wrow[h];
        #pragma unroll
        for (int o = 16; o > 0; o >>= 1) s += __shfl_xor_sync(0xffffffffu, s, o);
        if (lane == 0) {
            float sg = 1.f / (1.f + expf(-s));
            sc[e] = sg;
            scc[e] = sg + gbias[e];
        }
    }
    __syncthreads();
    if (tid == 0) {
        float gsc[NGROUP];
        #pragma unroll
        for (int g = 0; g < NGROUP; g++) {
            float m1 = -1e30f, m2 = -1e30f;
            for (int j = 0; j < GSIZE; j++) {
                float v = scc[g * GSIZE + j];
                if (v > m1) { m2 = m1; m1 = v; }
                else if (v > m2) { m2 = v; }
            }
            gsc[g] = m1 + m2;
        }
        bool gm[NGROUP] = {false, false, false, false};
        {
            float tg[NGROUP];
            #pragma unroll
            for (int g = 0; g < NGROUP; g++) tg[g] = gsc[g];
            for (int k = 0; k < TOPKG; k++) {
                int bi = 0; float bv = tg[0];
                for (int g = 1; g < NGROUP; g++) if (tg[g] > bv) { bv = tg[g]; bi = g; }
                gm[bi] = true; tg[bi] = -1e30f;
            }
        }
        float tmp[E_NUM];
        for (int e = 0; e < E_NUM; e++) tmp[e] = gm[e / GSIZE] ? scc[e] : 0.0f;
        int ids[TOPK]; float ws[TOPK]; float wsum = 0.f;
        for (int k = 0; k < TOPK; k++) {
            int bi = 0; float bv = tmp[0];
            for (int e = 1; e < E_NUM; e++) if (tmp[e] > bv) { bv = tmp[e]; bi = e; }
            ids[k] = bi; tmp[bi] = -1e30f;
            ws[k] = sc[bi]; wsum += ws[k];
        }
        float inv = 1.f / wsum;
        for (int k = 0; k < TOPK; k++) {
            g_tid_ids[t * TOPK + k] = ids[k];
            g_tid_w[t * TOPK + k] = ws[k] * inv;
            atomicAdd(&g_count[ids[k]], 1);
        }
    }
}

__global__ void scan_kernel() {
    if (threadIdx.x == 0) {
        int acc = 0;
        for (int e = 0; e < E_NUM; e++) {
            g_offset[e] = acc; g_cursor[e] = acc; acc += g_count[e];
        }
    }
}

__global__ void fill_kernel() {
    int i = blockIdx.x * 256 + threadIdx.x;
    if (i >= T_TOK * TOPK) return;
    int e = g_tid_ids[i];
    int pos = atomicAdd(&g_cursor[e], 1);
    g_pair_token[pos] = i / TOPK;
    g_pair_w[pos]     = g_tid_w[i];
}

__global__ void zero_out_kernel(float4* o) {
    int i = blockIdx.x * 256 + threadIdx.x;
    if (i < T_TOK * H_DIM / 4) o[i] = make_float4(0.f, 0.f, 0.f, 0.f);
}

// ============================================================================
// GEMM 1 (fp16 2-term): X[M,2048] @ W[2048, 64(gate)+64(up)] -> act, SiLU*mul
// BM=128, BN=64(+64 up), BK=16. D = Ah*Bh + Al*Bh  (A split exact, B single RN)
// SMEM uint layout per buffer: A_hi[128*12], A_lo[128*12], Bg[64*12], Bu[64*12]
// ============================================================================
#define SA 12
#define G1_A  (128 * SA)                  // uints per A matrix
#define G1_B  (64 * SA)                   // uints per B matrix
#define G1_BUF (2 * G1_A + 2 * G1_B)      // uints per buffer = 4608
#define G1_SMEM (2 * G1_BUF * 4)          // bytes = 36864

__global__ __launch_bounds__(256, 2)
void mma_gateup_kernel(const float* __restrict__ X,
                       const float* __restrict__ Wgu,
                       const float* __restrict__ Sgu) {
    extern __shared__ uint32_t smu[];
    const int e = blockIdx.z;
    const bool routed = (e < E_NUM);
    const int M = routed ? g_count[e] : T_TOK;
    const int m0 = blockIdx.y * 128;
    if (m0 >= M) return;
    const int n0 = blockIdx.x * 64;
    const float* W = routed ? (Wgu + (size_t)e * H_DIM * I2) : Sgu;
    const int off = routed ? g_offset[e] : 0;
    float* act = routed ? (g_act + (size_t)off * I_DIM) : g_act_sh;

    const int tid = threadIdx.x;
    const int lane = tid & 31, wid = tid >> 5;
    const int g = lane >> 2, tg = lane & 3;
    const int wm = (wid >> 1) * 32, wn = (wid & 1) * 32;

    // A fill: row = tid>>1, k-base cb = (tid&1)*8
    const int arow_i = tid >> 1, cb = (tid & 1) * 8;
    int ar = m0 + arow_i;
    int tokr = (ar < M) ? ar : m0;
    if (routed) tokr = g_pair_token[off + tokr];
    const float* Arow = X + (size_t)tokr * H_DIM;
    // B fill: n = tid&63, kpair-base bkp = tid>>6 -> kpairs {bkp, bkp+4}
    const int bn = tid & 63, bkp = tid >> 6;
    const float* Bgp = W + n0 + bn;
    const float* Bup = W + n0 + bn + I_DIM;

    float cg[2][4][4], cu[2][4][4];
    #pragma unroll
    for (int a = 0; a < 2; a++)
        #pragma unroll
        for (int b = 0; b < 4; b++)
            #pragma unroll
            for (int c = 0; c < 4; c++) { cg[a][b][c] = 0.f; cu[a][b][c] = 0.f; }

    float4 pa0, pa1;
    float pg[4], pu[4];
    const int NK = H_DIM / 16;   // 128

    // prologue load kt=0
    pa0 = *(const float4*)(Arow + cb);
    pa1 = *(const float4*)(Arow + cb + 4);
    pg[0] = Bgp[(size_t)(2 * bkp) * I2];     pg[1] = Bgp[(size_t)(2 * bkp + 1) * I2];
    pg[2] = Bgp[(size_t)(2 * bkp + 8) * I2]; pg[3] = Bgp[(size_t)(2 * bkp + 9) * I2];
    pu[0] = Bup[(size_t)(2 * bkp) * I2];     pu[1] = Bup[(size_t)(2 * bkp + 1) * I2];
    pu[2] = Bup[(size_t)(2 * bkp + 8) * I2]; pu[3] = Bup[(size_t)(2 * bkp + 9) * I2];

    {
        uint32_t* Ah = smu;
        uint32_t* Al = Ah + G1_A;
        uint32_t* Bg = Al + G1_A;
        uint32_t* Bu = Bg + G1_B;
        uint32_t h, l;
        int abase = arow_i * SA + cb / 2;
        split2h(pa0.x, pa0.y, h, l); Ah[abase + 0] = h; Al[abase + 0] = l;
        split2h(pa0.z, pa0.w, h, l); Ah[abase + 1] = h; Al[abase + 1] = l;
        split2h(pa1.x, pa1.y, h, l); Ah[abase + 2] = h; Al[abase + 2] = l;
        split2h(pa1.z, pa1.w, h, l); Ah[abase + 3] = h; Al[abase + 3] = l;
        int bbase = bn * SA + bkp;
        Bg[bbase]     = pack2h(pg[0], pg[1]);
        Bg[bbase + 4] = pack2h(pg[2], pg[3]);
        Bu[bbase]     = pack2h(pu[0], pu[1]);
        Bu[bbase + 4] = pack2h(pu[2], pu[3]);
    }
    __syncthreads();

    for (int kt = 0; kt < NK; kt++) {
        if (kt + 1 < NK) {
            const int k0 = (kt + 1) * 16;
            pa0 = *(const float4*)(Arow + k0 + cb);
            pa1 = *(const float4*)(Arow + k0 + cb + 4);
            pg[0] = Bgp[(size_t)(k0 + 2 * bkp) * I2];     pg[1] = Bgp[(size_t)(k0 + 2 * bkp + 1) * I2];
            pg[2] = Bgp[(size_t)(k0 + 2 * bkp + 8) * I2]; pg[3] = Bgp[(size_t)(k0 + 2 * bkp + 9) * I2];
            pu[0] = Bup[(size_t)(k0 + 2 * bkp) * I2];     pu[1] = Bup[(size_t)(k0 + 2 * bkp + 1) * I2];
            pu[2] = Bup[(size_t)(k0 + 2 * bkp + 8) * I2]; pu[3] = Bup[(size_t)(k0 + 2 * bkp + 9) * I2];
        }
        {
            const uint32_t* Ah = smu + (kt & 1) * G1_BUF;
            const uint32_t* Al = Ah + G1_A;
            const uint32_t* Bg = Al + G1_A;
            const uint32_t* Bu = Bg + G1_B;
            uint32_t ah[2][4], al[2][4];
            #pragma unroll
            for (int mt = 0; mt < 2; mt++) {
                const int r0 = wm + mt * 16;
                const int i0 = (r0 + g) * SA;
                const int i1 = (r0 + g + 8) * SA;
                ah[mt][0] = Ah[i0 + tg];     ah[mt][1] = Ah[i1 + tg];
                ah[mt][2] = Ah[i0 + tg + 4]; ah[mt][3] = Ah[i1 + tg + 4];
                al[mt][0] = Al[i0 + tg];     al[mt][1] = Al[i1 + tg];
                al[mt][2] = Al[i0 + tg + 4]; al[mt][3] = Al[i1 + tg + 4];
            }
            #pragma unroll
            for (int nt = 0; nt < 4; nt++) {
                const int nb = (wn + nt * 8 + g) * SA;
                uint32_t bg0 = Bg[nb + tg], bg1 = Bg[nb + tg + 4];
                uint32_t bu0 = Bu[nb + tg], bu1 = Bu[nb + tg + 4];
                #pragma unroll
                for (int mt = 0; mt < 2; mt++) {
                    mmah(cg[mt][nt], ah[mt][0], ah[mt][1], ah[mt][2], ah[mt][3], bg0, bg1);
                    mmah(cg[mt][nt], al[mt][0], al[mt][1], al[mt][2], al[mt][3], bg0, bg1);
                    mmah(cu[mt][nt], ah[mt][0], ah[mt][1], ah[mt][2], ah[mt][3], bu0, bu1);
                    mmah(cu[mt][nt], al[mt][0], al[mt][1], al[mt][2], al[mt][3], bu0, bu1);
                }
            }
        }
        __syncthreads();
        if (kt + 1 < NK) {
            uint32_t* Ah = smu + ((kt + 1) & 1) * G1_BUF;
            uint32_t* Al = Ah + G1_A;
            uint32_t* Bg = Al + G1_A;
            uint32_t* Bu = Bg + G1_B;
            uint32_t h, l;
            int abase = arow_i * SA + cb / 2;
            split2h(pa0.x, pa0.y, h, l); Ah[abase + 0] = h; Al[abase + 0] = l;
            split2h(pa0.z, pa0.w, h, l); Ah[abase + 1] = h; Al[abase + 1] = l;
            split2h(pa1.x, pa1.y, h, l); Ah[abase + 2] = h; Al[abase + 2] = l;
            split2h(pa1.z, pa1.w, h, l); Ah[abase + 3] = h; Al[abase + 3] = l;
            int bbase = bn * SA + bkp;
            Bg[bbase]     = pack2h(pg[0], pg[1]);
            Bg[bbase + 4] = pack2h(pg[2], pg[3]);
            Bu[bbase]     = pack2h(pu[0], pu[1]);
            Bu[bbase + 4] = pack2h(pu[2], pu[3]);
            __syncthreads();
        }
    }

    // epilogue: SiLU(gate)*up -> act
    #pragma unroll
    for (int mt = 0; mt < 2; mt++) {
        const int r1 = m0 + wm + mt * 16 + g;
        const int r2 = r1 + 8;
        #pragma unroll
        for (int nt = 0; nt < 4; nt++) {
            const int col = n0 + wn + nt * 8 + 2 * tg;
            if (r1 < M) {
                float2 o;
                o.x = silu(cg[mt][nt][0]) * cu[mt][nt][0];
                o.y = silu(cg[mt][nt][1]) * cu[mt][nt][1];
                *(float2*)(act + (size_t)r1 * I_DIM + col) = o;
            }
            if (r2 < M) {
                float2 o;
                o.x = silu(cg[mt][nt][2]) * cu[mt][nt][2];
                o.y = silu(cg[mt][nt][3]) * cu[mt][nt][3];
                *(float2*)(act + (size_t)r2 * I_DIM + col) = o;
            }
        }
    }
}

// ============================================================================
// GEMM 2 (fp16 2-term): act[M,768] @ Wd[768,2048] -> weighted atomicAdd out
// BM=128, BN=128, BK=16. 8 warps: warp tile 32x64.
// ============================================================================
#define G2_A  (128 * SA)
#define G2_B  (128 * SA)
#define G2_BUF (2 * G2_A + G2_B)          // uints = 4608
#define G2_SMEM (2 * G2_BUF * 4)          // 36864

__global__ __launch_bounds__(256, 2)
void mma_down_kernel(const float* __restrict__ Wd,
                     const float* __restrict__ Sd,
                     float* __restrict__ out) {
    extern __shared__ uint32_t smu[];
    const int e = blockIdx.z;
    const bool routed = (e < E_NUM);
    const int M = routed ? g_count[e] : T_TOK;
    const int m0 = blockIdx.y * 128;
    if (m0 >= M) return;
    const int n0 = blockIdx.x * 128;
    const float* W = routed ? (Wd + (size_t)e * I_DIM * H_DIM) : Sd;
    const int off = routed ? g_offset[e] : 0;
    const float* A = routed ? (g_act + (size_t)off * I_DIM) : g_act_sh;

    const int tid = threadIdx.x;
    const int lane = tid & 31, wid = tid >> 5;
    const int g = lane >> 2, tg = lane & 3;
    const int wm = (wid >> 1) * 32, wn = (wid & 1) * 64;

    const int arow_i = tid >> 1, cb = (tid & 1) * 8;
    int ar = m0 + arow_i;
    const float* Arow = A + (size_t)((ar < M) ? ar : m0) * I_DIM;
    const int bn = tid & 127, bkp = tid >> 7;     // bkp in {0,1} -> kpairs {bkp, bkp+2, bkp+4, bkp+6}
    const float* Bp = W + n0 + bn;

    float cc[2][8][4];
    #pragma unroll
    for (int a = 0; a < 2; a++)
        #pragma unroll
        for (int b = 0; b < 8; b++)
            #pragma unroll
            for (int c = 0; c < 4; c++) cc[a][b][c] = 0.f;

    float4 pa0, pa1;
    float pb[8];
    const int NK = I_DIM / 16;    // 48

    pa0 = *(const float4*)(Arow + cb);
    pa1 = *(const float4*)(Arow + cb + 4);
    #pragma unroll
    for (int j = 0; j < 4; j++) {
        int kp = bkp + 2 * j;
        pb[2 * j]     = Bp[(size_t)(2 * kp) * H_DIM];
        pb[2 * j + 1] = Bp[(size_t)(2 * kp + 1) * H_DIM];
    }
    {
        uint32_t* Ah = smu;
        uint32_t* Al = Ah + G2_A;
        uint32_t* Bh = Al + G2_A;
        uint32_t h, l;
        int abase = arow_i * SA + cb / 2;
        split2h(pa0.x, pa0.y, h, l); Ah[abase + 0] = h; Al[abase + 0] = l;
        split2h(pa0.z, pa0.w, h, l); Ah[abase + 1] = h; Al[abase + 1] = l;
        split2h(pa1.x, pa1.y, h, l); Ah[abase + 2] = h; Al[abase + 2] = l;
        split2h(pa1.z, pa1.w, h, l); Ah[abase + 3] = h; Al[abase + 3] = l;
        #pragma unroll
        for (int j = 0; j < 4; j++) {
            int kp = bkp + 2 * j;
            Bh[bn * SA + kp] = pack2h(pb[2 * j], pb[2 * j + 1]);
        }
    }
    __syncthreads();

    for (int kt = 0; kt < NK; kt++) {
        if (kt + 1 < NK) {
            const int k0 = (kt + 1) * 16;
            pa0 = *(const float4*)(Arow + k0 + cb);
            pa1 = *(const float4*)(Arow + k0 + cb + 4);
            #pragma unroll
            for (int j = 0; j < 4; j++) {
                int kp = bkp + 2 * j;
                pb[2 * j]     = Bp[(size_t)(k0 + 2 * kp) * H_DIM];
                pb[2 * j + 1] = Bp[(size_t)(k0 + 2 * kp + 1) * H_DIM];
            }
        }
        {
            const uint32_t* Ah = smu + (kt & 1) * G2_BUF;
            const uint32_t* Al = Ah + G2_A;
            const uint32_t* Bh = Al + G2_A;
            uint32_t ah[2][4], al[2][4];
            #pragma unroll
            for (int mt = 0; mt < 2; mt++) {
                const int r0 = wm + mt * 16;
                const int i0 = (r0 + g) * SA;
                const int i1 = (r0 + g + 8) * SA;
                ah[mt][0] = Ah[i0 + tg];     ah[mt][1] = Ah[i1 + tg];
                ah[mt][2] = Ah[i0 + tg + 4]; ah[mt][3] = Ah[i1 + tg + 4];
                al[mt][0] = Al[i0 + tg];     al[mt][1] = Al[i1 + tg];
                al[mt][2] = Al[i0 + tg + 4]; al[mt][3] = Al[i1 + tg + 4];
            }
            #pragma unroll
            for (int nt = 0; nt < 8; nt++) {
                const int nb = (wn + nt * 8 + g) * SA;
                uint32_t bh0 = Bh[nb + tg], bh1 = Bh[nb + tg + 4];
                #pragma unroll
                for (int mt = 0; mt < 2; mt++) {
                    mmah(cc[mt][nt], ah[mt][0], ah[mt][1], ah[mt][2], ah[mt][3], bh0, bh1);
                    mmah(cc[mt][nt], al[mt][0], al[mt][1], al[mt][2], al[mt][3], bh0, bh1);
                }
            }
        }
        __syncthreads();
        if (kt + 1 < NK) {
            uint32_t* Ah = smu + ((kt + 1) & 1) * G2_BUF;
            uint32_t* Al = Ah + G2_A;
            uint32_t* Bh = Al + G2_A;
            uint32_t h, l;
            int abase = arow_i * SA + cb / 2;
            split2h(pa0.x, pa0.y, h, l); Ah[abase + 0] = h; Al[abase + 0] = l;
            split2h(pa0.z, pa0.w, h, l); Ah[abase + 1] = h; Al[abase + 1] = l;
            split2h(pa1.x, pa1.y, h, l); Ah[abase + 2] = h; Al[abase + 2] = l;
            split2h(pa1.z, pa1.w, h, l); Ah[abase + 3] = h; Al[abase + 3] = l;
            #pragma unroll
            for (int j = 0; j < 4; j++) {
                int kp = bkp + 2 * j;
                Bh[bn * SA + kp] = pack2h(pb[2 * j], pb[2 * j + 1]);
            }
            __syncthreads();
        }
    }

    // epilogue: weighted combine via atomics
    #pragma unroll
    for (int mt = 0; mt < 2; mt++) {
        const int r1 = m0 + wm + mt * 16 + g;
        const int r2 = r1 + 8;
        int tok1 = 0, tok2 = 0;
        float s1 = 0.f, s2 = 0.f;
        bool ok1 = (r1 < M), ok2 = (r2 < M);
        if (ok1) {
            if (routed) { tok1 = g_pair_token[off + r1]; s1 = g_pair_w[off + r1] * RSCALE; }
            else        { tok1 = r1; s1 = 1.0f; }
        }
        if (ok2) {
            if (routed) { tok2 = g_pair_token[off + r2]; s2 = g_pair_w[off + r2] * RSCALE; }
            else        { tok2 = r2; s2 = 1.0f; }
        }
        float* o1 = out + (size_t)tok1 * H_DIM;
        float* o2 = out + (size_t)tok2 * H_DIM;
        #pragma unroll
        for (int nt = 0; nt < 8; nt++) {
            const int col = n0 + wn + nt * 8 + 2 * tg;
            if (ok1) {
                atomicAdd(o1 + col,     cc[mt][nt][0] * s1);
                atomicAdd(o1 + col + 1, cc[mt][nt][1] * s1);
            }
            if (ok2) {
                atomicAdd(o2 + col,     cc[mt][nt][2] * s2);
                atomicAdd(o2 + col + 1, cc[mt][nt][3] * s2);
            }
        }
    }
}

// ---------------- launch ---------------------------------------------------
extern "C" void kernel_launch(void* const* d_in, const int* in_sizes, int n_in,
                              void* d_out, int out_size) {
    (void)in_sizes; (void)n_in; (void)out_size;
    const float* hidden    = (const float*)d_in[0];
    const float* gate_w    = (const float*)d_in[1];
    const float* gate_bias = (const float*)d_in[2];
    const float* w_gate_up = (const float*)d_in[3];
    const float* w_down    = (const float*)d_in[4];
    const float* s_gate_up = (const float*)d_in[5];
    const float* s_down    = (const float*)d_in[6];
    float* out = (float*)d_out;

    cudaFuncSetAttribute(mma_gateup_kernel, cudaFuncAttributeMaxDynamicSharedMemorySize, G1_SMEM);
    cudaFuncSetAttribute(mma_down_kernel,   cudaFuncAttributeMaxDynamicSharedMemorySize, G2_SMEM);

    init_kernel<<<1, 32>>>();
    routing_kernel<<<T_TOK, 256>>>(hidden, gate_w, gate_bias);
    scan_kernel<<<1, 32>>>();
    fill_kernel<<<(T_TOK * TOPK + 255) / 256, 256>>>();
    zero_out_kernel<<<(T_TOK * H_DIM / 4 + 255) / 256, 256>>>((float4*)out);

    {
        dim3 grid(I_DIM / 64, T_TOK / 128, E_NUM + 1);    // (12, 8, 33)
        mma_gateup_kernel<<<grid, 256, G1_SMEM>>>(hidden, w_gate_up, s_gate_up);
    }
    {
        dim3 grid(H_DIM / 128, T_TOK / 128, E_NUM + 1);   // (16, 8, 33)
        mma_down_kernel<<<grid, 256, G2_SMEM>>>(w_down, s_down, out);
    }
}

// round 11
// speedup vs baseline: 3.4582x; 1.1814x over previous
#include <cuda_runtime.h>
#include <cuda_fp16.h>
#include <math.h>
#include <stdint.h>

#define T_TOK 1024
#define H_DIM 2048
#define E_NUM 32
#define I_DIM 768
#define I2    1536
#define TOPK  8
#define NGROUP 4
#define GSIZE  8
#define TOPKG  2
#define RSCALE 2.5f

// ---------------- scratch -------------------------------------------------
__device__ int   g_count[E_NUM];
__device__ int   g_offset[E_NUM];
__device__ int   g_cursor[E_NUM];
__device__ int   g_pair_token[T_TOK * TOPK];
__device__ float g_pair_w[T_TOK * TOPK];
__device__ int   g_tid_ids[T_TOK * TOPK];
__device__ float g_tid_w[T_TOK * TOPK];
__device__ float g_act[(size_t)T_TOK * TOPK * I_DIM];   // routed activations
__device__ float g_act_sh[(size_t)T_TOK * I_DIM];       // shared-expert activations

// ---------------- helpers -------------------------------------------------
__device__ __forceinline__ uint32_t pack2h(float v0, float v1) {
    uint32_t r;
    asm("cvt.rn.f16x2.f32 %0, %1, %2;" : "=r"(r) : "f"(v1), "f"(v0));
    return r;
}
__device__ __forceinline__ void mmah(float* c,
                                     uint32_t a0, uint32_t a1, uint32_t a2, uint32_t a3,
                                     uint32_t b0, uint32_t b1) {
    asm volatile("mma.sync.aligned.m16n8k16.row.col.f32.f16.f16.f32 "
                 "{%0,%1,%2,%3}, {%4,%5,%6,%7}, {%8,%9}, {%0,%1,%2,%3};"
                 : "+f"(c[0]), "+f"(c[1]), "+f"(c[2]), "+f"(c[3])
                 : "r"(a0), "r"(a1), "r"(a2), "r"(a3), "r"(b0), "r"(b1));
}
__device__ __forceinline__ float silu(float x) { return x / (1.f + expf(-x)); }

// ---------------- init / routing / scan / fill (proven) ------------------
__global__ void init_kernel() {
    int i = threadIdx.x;
    if (i < E_NUM) { g_count[i] = 0; g_cursor[i] = 0; g_offset[i] = 0; }
}

__global__ void routing_kernel(const float* __restrict__ x,
                               const float* __restrict__ gw,
                               const float* __restrict__ gbias) {
    int t = blockIdx.x;
    __shared__ float xs[H_DIM];
    __shared__ float sc[E_NUM];
    __shared__ float scc[E_NUM];
    int tid = threadIdx.x;
    for (int h = tid; h < H_DIM; h += 256) xs[h] = x[(size_t)t * H_DIM + h];
    __syncthreads();
    int warp = tid >> 5, lane = tid & 31;
    for (int e = warp; e < E_NUM; e += 8) {
        const float* wrow = gw + (size_t)e * H_DIM;
        float s = 0.f;
        for (int h = lane; h < H_DIM; h += 32) s += xs[h] * wrow[h];
        #pragma unroll
        for (int o = 16; o > 0; o >>= 1) s += __shfl_xor_sync(0xffffffffu, s, o);
        if (lane == 0) {
            float sg = 1.f / (1.f + expf(-s));
            sc[e] = sg;
            scc[e] = sg + gbias[e];
        }
    }
    __syncthreads();
    if (tid == 0) {
        float gsc[NGROUP];
        #pragma unroll
        for (int g = 0; g < NGROUP; g++) {
            float m1 = -1e30f, m2 = -1e30f;
            for (int j = 0; j < GSIZE; j++) {
                float v = scc[g * GSIZE + j];
                if (v > m1) { m2 = m1; m1 = v; }
                else if (v > m2) { m2 = v; }
            }
            gsc[g] = m1 + m2;
        }
        bool gm[NGROUP] = {false, false, false, false};
        {
            float tg[NGROUP];
            #pragma unroll
            for (int g = 0; g < NGROUP; g++) tg[g] = gsc[g];
            for (int k = 0; k < TOPKG; k++) {
                int bi = 0; float bv = tg[0];
                for (int g = 1; g < NGROUP; g++) if (tg[g] > bv) { bv = tg[g]; bi = g; }
                gm[bi] = true; tg[bi] = -1e30f;
            }
        }
        float tmp[E_NUM];
        for (int e = 0; e < E_NUM; e++) tmp[e] = gm[e / GSIZE] ? scc[e] : 0.0f;
        int ids[TOPK]; float ws[TOPK]; float wsum = 0.f;
        for (int k = 0; k < TOPK; k++) {
            int bi = 0; float bv = tmp[0];
            for (int e = 1; e < E_NUM; e++) if (tmp[e] > bv) { bv = tmp[e]; bi = e; }
            ids[k] = bi; tmp[bi] = -1e30f;
            ws[k] = sc[bi]; wsum += ws[k];
        }
        float inv = 1.f / wsum;
        for (int k = 0; k < TOPK; k++) {
            g_tid_ids[t * TOPK + k] = ids[k];
            g_tid_w[t * TOPK + k] = ws[k] * inv;
            atomicAdd(&g_count[ids[k]], 1);
        }
    }
}

__global__ void scan_kernel() {
    if (threadIdx.x == 0) {
        int acc = 0;
        for (int e = 0; e < E_NUM; e++) {
            g_offset[e] = acc; g_cursor[e] = acc; acc += g_count[e];
        }
    }
}

__global__ void fill_kernel() {
    int i = blockIdx.x * 256 + threadIdx.x;
    if (i >= T_TOK * TOPK) return;
    int e = g_tid_ids[i];
    int pos = atomicAdd(&g_cursor[e], 1);
    g_pair_token[pos] = i / TOPK;
    g_pair_w[pos]     = g_tid_w[i];
}

__global__ void zero_out_kernel(float4* o) {
    int i = blockIdx.x * 256 + threadIdx.x;
    if (i < T_TOK * H_DIM / 4) o[i] = make_float4(0.f, 0.f, 0.f, 0.f);
}

// ============================================================================
// GEMM 1 (fp16 single): X[M,2048] @ W[2048, 64(gate)+64(up)] -> act, SiLU*mul
// BM=128, BN=64(+64 up), BK=16. SMEM per buffer: A[128*12], Bg[64*12], Bu[64*12]
// ============================================================================
#define SA 12
#define G1_A  (128 * SA)
#define G1_B  (64 * SA)
#define G1_BUF (G1_A + 2 * G1_B)          // uints per buffer = 3072
#define G1_SMEM (2 * G1_BUF * 4)          // bytes = 24576

__global__ __launch_bounds__(256, 2)
void mma_gateup_kernel(const float* __restrict__ X,
                       const float* __restrict__ Wgu,
                       const float* __restrict__ Sgu) {
    extern __shared__ uint32_t smu[];
    const int e = blockIdx.z;
    const bool routed = (e < E_NUM);
    const int M = routed ? g_count[e] : T_TOK;
    const int m0 = blockIdx.y * 128;
    if (m0 >= M) return;
    const int n0 = blockIdx.x * 64;
    const float* W = routed ? (Wgu + (size_t)e * H_DIM * I2) : Sgu;
    const int off = routed ? g_offset[e] : 0;
    float* act = routed ? (g_act + (size_t)off * I_DIM) : g_act_sh;

    const int tid = threadIdx.x;
    const int lane = tid & 31, wid = tid >> 5;
    const int g = lane >> 2, tg = lane & 3;
    const int wm = (wid >> 1) * 32, wn = (wid & 1) * 32;

    const int arow_i = tid >> 1, cb = (tid & 1) * 8;
    int ar = m0 + arow_i;
    int tokr = (ar < M) ? ar : m0;
    if (routed) tokr = g_pair_token[off + tokr];
    const float* Arow = X + (size_t)tokr * H_DIM;
    const int bn = tid & 63, bkp = tid >> 6;
    const float* Bgp = W + n0 + bn;
    const float* Bup = W + n0 + bn + I_DIM;

    float cg[2][4][4], cu[2][4][4];
    #pragma unroll
    for (int a = 0; a < 2; a++)
        #pragma unroll
        for (int b = 0; b < 4; b++)
            #pragma unroll
            for (int c = 0; c < 4; c++) { cg[a][b][c] = 0.f; cu[a][b][c] = 0.f; }

    float4 pa0, pa1;
    float pg[4], pu[4];
    const int NK = H_DIM / 16;   // 128

    pa0 = *(const float4*)(Arow + cb);
    pa1 = *(const float4*)(Arow + cb + 4);
    pg[0] = Bgp[(size_t)(2 * bkp) * I2];     pg[1] = Bgp[(size_t)(2 * bkp + 1) * I2];
    pg[2] = Bgp[(size_t)(2 * bkp + 8) * I2]; pg[3] = Bgp[(size_t)(2 * bkp + 9) * I2];
    pu[0] = Bup[(size_t)(2 * bkp) * I2];     pu[1] = Bup[(size_t)(2 * bkp + 1) * I2];
    pu[2] = Bup[(size_t)(2 * bkp + 8) * I2]; pu[3] = Bup[(size_t)(2 * bkp + 9) * I2];

    {
        uint32_t* Ah = smu;
        uint32_t* Bg = Ah + G1_A;
        uint32_t* Bu = Bg + G1_B;
        int abase = arow_i * SA + cb / 2;
        Ah[abase + 0] = pack2h(pa0.x, pa0.y);
        Ah[abase + 1] = pack2h(pa0.z, pa0.w);
        Ah[abase + 2] = pack2h(pa1.x, pa1.y);
        Ah[abase + 3] = pack2h(pa1.z, pa1.w);
        int bbase = bn * SA + bkp;
        Bg[bbase]     = pack2h(pg[0], pg[1]);
        Bg[bbase + 4] = pack2h(pg[2], pg[3]);
        Bu[bbase]     = pack2h(pu[0], pu[1]);
        Bu[bbase + 4] = pack2h(pu[2], pu[3]);
    }
    __syncthreads();

    for (int kt = 0; kt < NK; kt++) {
        if (kt + 1 < NK) {
            const int k0 = (kt + 1) * 16;
            pa0 = *(const float4*)(Arow + k0 + cb);
            pa1 = *(const float4*)(Arow + k0 + cb + 4);
            pg[0] = Bgp[(size_t)(k0 + 2 * bkp) * I2];     pg[1] = Bgp[(size_t)(k0 + 2 * bkp + 1) * I2];
            pg[2] = Bgp[(size_t)(k0 + 2 * bkp + 8) * I2]; pg[3] = Bgp[(size_t)(k0 + 2 * bkp + 9) * I2];
            pu[0] = Bup[(size_t)(k0 + 2 * bkp) * I2];     pu[1] = Bup[(size_t)(k0 + 2 * bkp + 1) * I2];
            pu[2] = Bup[(size_t)(k0 + 2 * bkp + 8) * I2]; pu[3] = Bup[(size_t)(k0 + 2 * bkp + 9) * I2];
        }
        {
            const uint32_t* Ah = smu + (kt & 1) * G1_BUF;
            const uint32_t* Bg = Ah + G1_A;
            const uint32_t* Bu = Bg + G1_B;
            uint32_t ah[2][4];
            #pragma unroll
            for (int mt = 0; mt < 2; mt++) {
                const int r0 = wm + mt * 16;
                const int i0 = (r0 + g) * SA;
                const int i1 = (r0 + g + 8) * SA;
                ah[mt][0] = Ah[i0 + tg];     ah[mt][1] = Ah[i1 + tg];
                ah[mt][2] = Ah[i0 + tg + 4]; ah[mt][3] = Ah[i1 + tg + 4];
            }
            #pragma unroll
            for (int nt = 0; nt < 4; nt++) {
                const int nb = (wn + nt * 8 + g) * SA;
                uint32_t bg0 = Bg[nb + tg], bg1 = Bg[nb + tg + 4];
                uint32_t bu0 = Bu[nb + tg], bu1 = Bu[nb + tg + 4];
                #pragma unroll
                for (int mt = 0; mt < 2; mt++) {
                    mmah(cg[mt][nt], ah[mt][0], ah[mt][1], ah[mt][2], ah[mt][3], bg0, bg1);
                    mmah(cu[mt][nt], ah[mt][0], ah[mt][1], ah[mt][2], ah[mt][3], bu0, bu1);
                }
            }
        }
        __syncthreads();
        if (kt + 1 < NK) {
            uint32_t* Ah = smu + ((kt + 1) & 1) * G1_BUF;
            uint32_t* Bg = Ah + G1_A;
            uint32_t* Bu = Bg + G1_B;
            int abase = arow_i * SA + cb / 2;
            Ah[abase + 0] = pack2h(pa0.x, pa0.y);
            Ah[abase + 1] = pack2h(pa0.z, pa0.w);
            Ah[abase + 2] = pack2h(pa1.x, pa1.y);
            Ah[abase + 3] = pack2h(pa1.z, pa1.w);
            int bbase = bn * SA + bkp;
            Bg[bbase]     = pack2h(pg[0], pg[1]);
            Bg[bbase + 4] = pack2h(pg[2], pg[3]);
            Bu[bbase]     = pack2h(pu[0], pu[1]);
            Bu[bbase + 4] = pack2h(pu[2], pu[3]);
            __syncthreads();
        }
    }

    // epilogue: SiLU(gate)*up -> act
    #pragma unroll
    for (int mt = 0; mt < 2; mt++) {
        const int r1 = m0 + wm + mt * 16 + g;
        const int r2 = r1 + 8;
        #pragma unroll
        for (int nt = 0; nt < 4; nt++) {
            const int col = n0 + wn + nt * 8 + 2 * tg;
            if (r1 < M) {
                float2 o;
                o.x = silu(cg[mt][nt][0]) * cu[mt][nt][0];
                o.y = silu(cg[mt][nt][1]) * cu[mt][nt][1];
                *(float2*)(act + (size_t)r1 * I_DIM + col) = o;
            }
            if (r2 < M) {
                float2 o;
                o.x = silu(cg[mt][nt][2]) * cu[mt][nt][2];
                o.y = silu(cg[mt][nt][3]) * cu[mt][nt][3];
                *(float2*)(act + (size_t)r2 * I_DIM + col) = o;
            }
        }
    }
}

// ============================================================================
// GEMM 2 (fp16 single): act[M,768] @ Wd[768,2048] -> weighted atomicAdd out
// BM=128, BN=128, BK=16. 8 warps: warp tile 32x64.
// ============================================================================
#define G2_A  (128 * SA)
#define G2_B  (128 * SA)
#define G2_BUF (G2_A + G2_B)              // uints = 3072
#define G2_SMEM (2 * G2_BUF * 4)          // 24576

__global__ __launch_bounds__(256, 2)
void mma_down_kernel(const float* __restrict__ Wd,
                     const float* __restrict__ Sd,
                     float* __restrict__ out) {
    extern __shared__ uint32_t smu[];
    const int e = blockIdx.z;
    const bool routed = (e < E_NUM);
    const int M = routed ? g_count[e] : T_TOK;
    const int m0 = blockIdx.y * 128;
    if (m0 >= M) return;
    const int n0 = blockIdx.x * 128;
    const float* W = routed ? (Wd + (size_t)e * I_DIM * H_DIM) : Sd;
    const int off = routed ? g_offset[e] : 0;
    const float* A = routed ? (g_act + (size_t)off * I_DIM) : g_act_sh;

    const int tid = threadIdx.x;
    const int lane = tid & 31, wid = tid >> 5;
    const int g = lane >> 2, tg = lane & 3;
    const int wm = (wid >> 1) * 32, wn = (wid & 1) * 64;

    const int arow_i = tid >> 1, cb = (tid & 1) * 8;
    int ar = m0 + arow_i;
    const float* Arow = A + (size_t)((ar < M) ? ar : m0) * I_DIM;
    const int bn = tid & 127, bkp = tid >> 7;
    const float* Bp = W + n0 + bn;

    float cc[2][8][4];
    #pragma unroll
    for (int a = 0; a < 2; a++)
        #pragma unroll
        for (int b = 0; b < 8; b++)
            #pragma unroll
            for (int c = 0; c < 4; c++) cc[a][b][c] = 0.f;

    float4 pa0, pa1;
    float pb[8];
    const int NK = I_DIM / 16;    // 48

    pa0 = *(const float4*)(Arow + cb);
    pa1 = *(const float4*)(Arow + cb + 4);
    #pragma unroll
    for (int j = 0; j < 4; j++) {
        int kp = bkp + 2 * j;
        pb[2 * j]     = Bp[(size_t)(2 * kp) * H_DIM];
        pb[2 * j + 1] = Bp[(size_t)(2 * kp + 1) * H_DIM];
    }
    {
        uint32_t* Ah = smu;
        uint32_t* Bh = Ah + G2_A;
        int abase = arow_i * SA + cb / 2;
        Ah[abase + 0] = pack2h(pa0.x, pa0.y);
        Ah[abase + 1] = pack2h(pa0.z, pa0.w);
        Ah[abase + 2] = pack2h(pa1.x, pa1.y);
        Ah[abase + 3] = pack2h(pa1.z, pa1.w);
        #pragma unroll
        for (int j = 0; j < 4; j++) {
            int kp = bkp + 2 * j;
            Bh[bn * SA + kp] = pack2h(pb[2 * j], pb[2 * j + 1]);
        }
    }
    __syncthreads();

    for (int kt = 0; kt < NK; kt++) {
        if (kt + 1 < NK) {
            const int k0 = (kt + 1) * 16;
            pa0 = *(const float4*)(Arow + k0 + cb);
            pa1 = *(const float4*)(Arow + k0 + cb + 4);
            #pragma unroll
            for (int j = 0; j < 4; j++) {
                int kp = bkp + 2 * j;
                pb[2 * j]     = Bp[(size_t)(k0 + 2 * kp) * H_DIM];
                pb[2 * j + 1] = Bp[(size_t)(k0 + 2 * kp + 1) * H_DIM];
            }
        }
        {
            const uint32_t* Ah = smu + (kt & 1) * G2_BUF;
            const uint32_t* Bh = Ah + G2_A;
            uint32_t ah[2][4];
            #pragma unroll
            for (int mt = 0; mt < 2; mt++) {
                const int r0 = wm + mt * 16;
                const int i0 = (r0 + g) * SA;
                const int i1 = (r0 + g + 8) * SA;
                ah[mt][0] = Ah[i0 + tg];     ah[mt][1] = Ah[i1 + tg];
                ah[mt][2] = Ah[i0 + tg + 4]; ah[mt][3] = Ah[i1 + tg + 4];
            }
            #pragma unroll
            for (int nt = 0; nt < 8; nt++) {
                const int nb = (wn + nt * 8 + g) * SA;
                uint32_t bh0 = Bh[nb + tg], bh1 = Bh[nb + tg + 4];
                #pragma unroll
                for (int mt = 0; mt < 2; mt++) {
                    mmah(cc[mt][nt], ah[mt][0], ah[mt][1], ah[mt][2], ah[mt][3], bh0, bh1);
                }
            }
        }
        __syncthreads();
        if (kt + 1 < NK) {
            uint32_t* Ah = smu + ((kt + 1) & 1) * G2_BUF;
            uint32_t* Bh = Ah + G2_A;
            int abase = arow_i * SA + cb / 2;
            Ah[abase + 0] = pack2h(pa0.x, pa0.y);
            Ah[abase + 1] = pack2h(pa0.z, pa0.w);
            Ah[abase + 2] = pack2h(pa1.x, pa1.y);
            Ah[abase + 3] = pack2h(pa1.z, pa1.w);
            #pragma unroll
            for (int j = 0; j < 4; j++) {
                int kp = bkp + 2 * j;
                Bh[bn * SA + kp] = pack2h(pb[2 * j], pb[2 * j + 1]);
            }
            __syncthreads();
        }
    }

    // epilogue: weighted combine via atomics
    #pragma unroll
    for (int mt = 0; mt < 2; mt++) {
        const int r1 = m0 + wm + mt * 16 + g;
        const int r2 = r1 + 8;
        int tok1 = 0, tok2 = 0;
        float s1 = 0.f, s2 = 0.f;
        bool ok1 = (r1 < M), ok2 = (r2 < M);
        if (ok1) {
            if (routed) { tok1 = g_pair_token[off + r1]; s1 = g_pair_w[off + r1] * RSCALE; }
            else        { tok1 = r1; s1 = 1.0f; }
        }
        if (ok2) {
            if (routed) { tok2 = g_pair_token[off + r2]; s2 = g_pair_w[off + r2] * RSCALE; }
            else        { tok2 = r2; s2 = 1.0f; }
        }
        float* o1 = out + (size_t)tok1 * H_DIM;
        float* o2 = out + (size_t)tok2 * H_DIM;
        #pragma unroll
        for (int nt = 0; nt < 8; nt++) {
            const int col = n0 + wn + nt * 8 + 2 * tg;
            if (ok1) {
                atomicAdd(o1 + col,     cc[mt][nt][0] * s1);
                atomicAdd(o1 + col + 1, cc[mt][nt][1] * s1);
            }
            if (ok2) {
                atomicAdd(o2 + col,     cc[mt][nt][2] * s2);
                atomicAdd(o2 + col + 1, cc[mt][nt][3] * s2);
            }
        }
    }
}

// ---------------- launch ---------------------------------------------------
extern "C" void kernel_launch(void* const* d_in, const int* in_sizes, int n_in,
                              void* d_out, int out_size) {
    (void)in_sizes; (void)n_in; (void)out_size;
    const float* hidden    = (const float*)d_in[0];
    const float* gate_w    = (const float*)d_in[1];
    const float* gate_bias = (const float*)d_in[2];
    const float* w_gate_up = (const float*)d_in[3];
    const float* w_down    = (const float*)d_in[4];
    const float* s_gate_up = (const float*)d_in[5];
    const float* s_down    = (const float*)d_in[6];
    float* out = (float*)d_out;

    cudaFuncSetAttribute(mma_gateup_kernel, cudaFuncAttributeMaxDynamicSharedMemorySize, G1_SMEM);
    cudaFuncSetAttribute(mma_down_kernel,   cudaFuncAttributeMaxDynamicSharedMemorySize, G2_SMEM);

    init_kernel<<<1, 32>>>();
    routing_kernel<<<T_TOK, 256>>>(hidden, gate_w, gate_bias);
    scan_kernel<<<1, 32>>>();
    fill_kernel<<<(T_TOK * TOPK + 255) / 256, 256>>>();
    zero_out_kernel<<<(T_TOK * H_DIM / 4 + 255) / 256, 256>>>((float4*)out);

    {
        dim3 grid(I_DIM / 64, T_TOK / 128, E_NUM + 1);    // (12, 8, 33)
        mma_gateup_kernel<<<grid, 256, G1_SMEM>>>(hidden, w_gate_up, s_gate_up);
    }
    {
        dim3 grid(H_DIM / 128, T_TOK / 128, E_NUM + 1);   // (16, 8, 33)
        mma_down_kernel<<<grid, 256, G2_SMEM>>>(w_down, s_down, out);
    }
}

// round 12
// speedup vs baseline: 3.8904x; 1.1250x over previous
#include <cuda_runtime.h>
#include <cuda_fp16.h>
#include <math.h>
#include <stdint.h>

#define T_TOK 1024
#define H_DIM 2048
#define E_NUM 32
#define I_DIM 768
#define I2    1536
#define TOPK  8
#define NGROUP 4
#define GSIZE  8
#define TOPKG  2
#define RSCALE 2.5f

// ---------------- scratch -------------------------------------------------
__device__ int   g_count[E_NUM];
__device__ int   g_offset[E_NUM];
__device__ int   g_cursor[E_NUM];
__device__ int   g_pair_token[T_TOK * TOPK];
__device__ float g_pair_w[T_TOK * TOPK];
__device__ int   g_tid_ids[T_TOK * TOPK];
__device__ float g_tid_w[T_TOK * TOPK];
__device__ float g_act[(size_t)T_TOK * TOPK * I_DIM];
__device__ float g_act_sh[(size_t)T_TOK * I_DIM];

// ---------------- helpers -------------------------------------------------
__device__ __forceinline__ uint32_t pack2h(float v0, float v1) {
    uint32_t r;
    asm("cvt.rn.f16x2.f32 %0, %1, %2;" : "=r"(r) : "f"(v1), "f"(v0));
    return r;
}
__device__ __forceinline__ uint32_t s2u(const void* p) {
    uint32_t a;
    asm("{ .reg .u64 t; cvta.to.shared.u64 t, %1; cvt.u32.u64 %0, t; }" : "=r"(a) : "l"(p));
    return a;
}
__device__ __forceinline__ void ldm4(uint32_t* d, uint32_t addr) {
    asm volatile("ldmatrix.sync.aligned.m8n8.x4.shared.b16 {%0,%1,%2,%3}, [%4];"
                 : "=r"(d[0]), "=r"(d[1]), "=r"(d[2]), "=r"(d[3]) : "r"(addr));
}
__device__ __forceinline__ void mmah(float* c,
                                     uint32_t a0, uint32_t a1, uint32_t a2, uint32_t a3,
                                     uint32_t b0, uint32_t b1) {
    asm volatile("mma.sync.aligned.m16n8k16.row.col.f32.f16.f16.f32 "
                 "{%0,%1,%2,%3}, {%4,%5,%6,%7}, {%8,%9}, {%0,%1,%2,%3};"
                 : "+f"(c[0]), "+f"(c[1]), "+f"(c[2]), "+f"(c[3])
                 : "r"(a0), "r"(a1), "r"(a2), "r"(a3), "r"(b0), "r"(b1));
}
__device__ __forceinline__ float silu(float x) { return x / (1.f + expf(-x)); }

// ---------------- init / routing / scan / fill (proven) ------------------
__global__ void init_kernel() {
    int i = threadIdx.x;
    if (i < E_NUM) { g_count[i] = 0; g_cursor[i] = 0; g_offset[i] = 0; }
}

__global__ void routing_kernel(const float* __restrict__ x,
                               const float* __restrict__ gw,
                               const float* __restrict__ gbias) {
    int t = blockIdx.x;
    __shared__ float xs[H_DIM];
    __shared__ float sc[E_NUM];
    __shared__ float scc[E_NUM];
    int tid = threadIdx.x;
    for (int h = tid; h < H_DIM; h += 256) xs[h] = x[(size_t)t * H_DIM + h];
    __syncthreads();
    int warp = tid >> 5, lane = tid & 31;
    for (int e = warp; e < E_NUM; e += 8) {
        const float* wrow = gw + (size_t)e * H_DIM;
        float s = 0.f;
        for (int h = lane; h < H_DIM; h += 32) s += xs[h] * wrow[h];
        #pragma unroll
        for (int o = 16; o > 0; o >>= 1) s += __shfl_xor_sync(0xffffffffu, s, o);
        if (lane == 0) {
            float sg = 1.f / (1.f + expf(-s));
            sc[e] = sg;
            scc[e] = sg + gbias[e];
        }
    }
    __syncthreads();
    if (tid == 0) {
        float gsc[NGROUP];
        #pragma unroll
        for (int g = 0; g < NGROUP; g++) {
            float m1 = -1e30f, m2 = -1e30f;
            for (int j = 0; j < GSIZE; j++) {
                float v = scc[g * GSIZE + j];
                if (v > m1) { m2 = m1; m1 = v; }
                else if (v > m2) { m2 = v; }
            }
            gsc[g] = m1 + m2;
        }
        bool gm[NGROUP] = {false, false, false, false};
        {
            float tg[NGROUP];
            #pragma unroll
            for (int g = 0; g < NGROUP; g++) tg[g] = gsc[g];
            for (int k = 0; k < TOPKG; k++) {
                int bi = 0; float bv = tg[0];
                for (int g = 1; g < NGROUP; g++) if (tg[g] > bv) { bv = tg[g]; bi = g; }
                gm[bi] = true; tg[bi] = -1e30f;
            }
        }
        float tmp[E_NUM];
        for (int e = 0; e < E_NUM; e++) tmp[e] = gm[e / GSIZE] ? scc[e] : 0.0f;
        int ids[TOPK]; float ws[TOPK]; float wsum = 0.f;
        for (int k = 0; k < TOPK; k++) {
            int bi = 0; float bv = tmp[0];
            for (int e = 1; e < E_NUM; e++) if (tmp[e] > bv) { bv = tmp[e]; bi = e; }
            ids[k] = bi; tmp[bi] = -1e30f;
            ws[k] = sc[bi]; wsum += ws[k];
        }
        float inv = 1.f / wsum;
        for (int k = 0; k < TOPK; k++) {
            g_tid_ids[t * TOPK + k] = ids[k];
            g_tid_w[t * TOPK + k] = ws[k] * inv;
            atomicAdd(&g_count[ids[k]], 1);
        }
    }
}

__global__ void scan_kernel() {
    if (threadIdx.x == 0) {
        int acc = 0;
        for (int e = 0; e < E_NUM; e++) {
            g_offset[e] = acc; g_cursor[e] = acc; acc += g_count[e];
        }
    }
}

__global__ void fill_kernel() {
    int i = blockIdx.x * 256 + threadIdx.x;
    if (i >= T_TOK * TOPK) return;
    int e = g_tid_ids[i];
    int pos = atomicAdd(&g_cursor[e], 1);
    g_pair_token[pos] = i / TOPK;
    g_pair_w[pos]     = g_tid_w[i];
}

__global__ void zero_out_kernel(float4* o) {
    int i = blockIdx.x * 256 + threadIdx.x;
    if (i < T_TOK * H_DIM / 4) o[i] = make_float4(0.f, 0.f, 0.f, 0.f);
}

// ============================================================================
// GEMM 1 (fp16, ldmatrix, 3-buffer ring): X @ W[gate|up] -> act with SiLU*mul
// BM=128, BN=64(+64), BK=16. SMEM slot: A[128*12], Bg[64*12], Bu[64*12] uints
// ============================================================================
#define SA 12
#define G1_A  (128 * SA)
#define G1_B  (64 * SA)
#define G1_BUF (G1_A + 2 * G1_B)          // 3072 uints/slot
#define G1_SMEM (3 * G1_BUF * 4)          // 36864 B

__global__ __launch_bounds__(256, 2)
void mma_gateup_kernel(const float* __restrict__ X,
                       const float* __restrict__ Wgu,
                       const float* __restrict__ Sgu) {
    extern __shared__ uint32_t smu[];
    const int e = blockIdx.z;
    const bool routed = (e < E_NUM);
    const int M = routed ? g_count[e] : T_TOK;
    const int m0 = blockIdx.y * 128;
    if (m0 >= M) return;
    const int n0 = blockIdx.x * 64;
    const float* W = routed ? (Wgu + (size_t)e * H_DIM * I2) : Sgu;
    const int off = routed ? g_offset[e] : 0;
    float* act = routed ? (g_act + (size_t)off * I_DIM) : g_act_sh;

    const int tid = threadIdx.x;
    const int lane = tid & 31, wid = tid >> 5;
    const int g = lane >> 2, tg = lane & 3;
    const int wm = (wid >> 1) * 32, wn = (wid & 1) * 32;
    const uint32_t smb = s2u(smu);

    const int arow_i = tid >> 1, cb = (tid & 1) * 8;
    int ar = m0 + arow_i;
    int tokr = (ar < M) ? ar : m0;
    if (routed) tokr = g_pair_token[off + tokr];
    const float* Arow = X + (size_t)tokr * H_DIM;
    const int bn = tid & 63, bkp = tid >> 6;
    const float* Bgp = W + n0 + bn;
    const float* Bup = W + n0 + bn + I_DIM;

    // ldmatrix byte offsets (slot-relative)
    const int lrow = lane & 15, lchunk = (lane >> 4) * 16;
    uint32_t aoff[2], bgoff[2], buoff[2];
    #pragma unroll
    for (int mt = 0; mt < 2; mt++)
        aoff[mt] = (uint32_t)((wm + mt * 16 + lrow) * SA * 4 + lchunk);
    #pragma unroll
    for (int p = 0; p < 2; p++) {
        bgoff[p] = (uint32_t)(G1_A * 4 + (wn + p * 16 + lrow) * SA * 4 + lchunk);
        buoff[p] = bgoff[p] + (uint32_t)(G1_B * 4);
    }

    float cg[2][4][4], cu[2][4][4];
    #pragma unroll
    for (int a = 0; a < 2; a++)
        #pragma unroll
        for (int b = 0; b < 4; b++)
            #pragma unroll
            for (int c = 0; c < 4; c++) { cg[a][b][c] = 0.f; cu[a][b][c] = 0.f; }

    float4 pa0, pa1;
    float pg[4], pu[4];
    const int NK = H_DIM / 16;   // 128
    const int abase = arow_i * SA + cb / 2;
    const int bbase = bn * SA + bkp;

    // prologue: tile0 -> regs -> slot0; tile1 -> regs
    pa0 = *(const float4*)(Arow + cb);
    pa1 = *(const float4*)(Arow + cb + 4);
    pg[0] = Bgp[(size_t)(2 * bkp) * I2];     pg[1] = Bgp[(size_t)(2 * bkp + 1) * I2];
    pg[2] = Bgp[(size_t)(2 * bkp + 8) * I2]; pg[3] = Bgp[(size_t)(2 * bkp + 9) * I2];
    pu[0] = Bup[(size_t)(2 * bkp) * I2];     pu[1] = Bup[(size_t)(2 * bkp + 1) * I2];
    pu[2] = Bup[(size_t)(2 * bkp + 8) * I2]; pu[3] = Bup[(size_t)(2 * bkp + 9) * I2];
    {
        uint32_t* Ah = smu;
        uint32_t* Bg = Ah + G1_A;
        uint32_t* Bu = Bg + G1_B;
        Ah[abase + 0] = pack2h(pa0.x, pa0.y);
        Ah[abase + 1] = pack2h(pa0.z, pa0.w);
        Ah[abase + 2] = pack2h(pa1.x, pa1.y);
        Ah[abase + 3] = pack2h(pa1.z, pa1.w);
        Bg[bbase]     = pack2h(pg[0], pg[1]);
        Bg[bbase + 4] = pack2h(pg[2], pg[3]);
        Bu[bbase]     = pack2h(pu[0], pu[1]);
        Bu[bbase + 4] = pack2h(pu[2], pu[3]);
    }
    if (NK > 1) {
        const int k0 = 16;
        pa0 = *(const float4*)(Arow + k0 + cb);
        pa1 = *(const float4*)(Arow + k0 + cb + 4);
        pg[0] = Bgp[(size_t)(k0 + 2 * bkp) * I2];     pg[1] = Bgp[(size_t)(k0 + 2 * bkp + 1) * I2];
        pg[2] = Bgp[(size_t)(k0 + 2 * bkp + 8) * I2]; pg[3] = Bgp[(size_t)(k0 + 2 * bkp + 9) * I2];
        pu[0] = Bup[(size_t)(k0 + 2 * bkp) * I2];     pu[1] = Bup[(size_t)(k0 + 2 * bkp + 1) * I2];
        pu[2] = Bup[(size_t)(k0 + 2 * bkp + 8) * I2]; pu[3] = Bup[(size_t)(k0 + 2 * bkp + 9) * I2];
    }

    int slot_c = 0;  // compute slot = kt % 3
    for (int kt = 0; kt < NK; kt++) {
        __syncthreads();
        int slot_s = slot_c + 1; if (slot_s == 3) slot_s = 0;
        if (kt + 1 < NK) {
            uint32_t* Ah = smu + slot_s * G1_BUF;
            uint32_t* Bg = Ah + G1_A;
            uint32_t* Bu = Bg + G1_B;
            Ah[abase + 0] = pack2h(pa0.x, pa0.y);
            Ah[abase + 1] = pack2h(pa0.z, pa0.w);
            Ah[abase + 2] = pack2h(pa1.x, pa1.y);
            Ah[abase + 3] = pack2h(pa1.z, pa1.w);
            Bg[bbase]     = pack2h(pg[0], pg[1]);
            Bg[bbase + 4] = pack2h(pg[2], pg[3]);
            Bu[bbase]     = pack2h(pu[0], pu[1]);
            Bu[bbase + 4] = pack2h(pu[2], pu[3]);
        }
        if (kt + 2 < NK) {
            const int k0 = (kt + 2) * 16;
            pa0 = *(const float4*)(Arow + k0 + cb);
            pa1 = *(const float4*)(Arow + k0 + cb + 4);
            pg[0] = Bgp[(size_t)(k0 + 2 * bkp) * I2];     pg[1] = Bgp[(size_t)(k0 + 2 * bkp + 1) * I2];
            pg[2] = Bgp[(size_t)(k0 + 2 * bkp + 8) * I2]; pg[3] = Bgp[(size_t)(k0 + 2 * bkp + 9) * I2];
            pu[0] = Bup[(size_t)(k0 + 2 * bkp) * I2];     pu[1] = Bup[(size_t)(k0 + 2 * bkp + 1) * I2];
            pu[2] = Bup[(size_t)(k0 + 2 * bkp + 8) * I2]; pu[3] = Bup[(size_t)(k0 + 2 * bkp + 9) * I2];
        }
        {
            const uint32_t sb = smb + (uint32_t)(slot_c * G1_BUF * 4);
            uint32_t a[2][4], bg[2][4], bu[2][4];
            #pragma unroll
            for (int mt = 0; mt < 2; mt++) ldm4(a[mt], sb + aoff[mt]);
            #pragma unroll
            for (int p = 0; p < 2; p++) { ldm4(bg[p], sb + bgoff[p]); ldm4(bu[p], sb + buoff[p]); }
            #pragma unroll
            for (int p = 0; p < 2; p++)
                #pragma unroll
                for (int s = 0; s < 2; s++) {
                    const int nt = p * 2 + s;
                    uint32_t g0 = bg[p][s], g1 = bg[p][s + 2];
                    uint32_t u0 = bu[p][s], u1 = bu[p][s + 2];
                    #pragma unroll
                    for (int mt = 0; mt < 2; mt++) {
                        mmah(cg[mt][nt], a[mt][0], a[mt][1], a[mt][2], a[mt][3], g0, g1);
                        mmah(cu[mt][nt], a[mt][0], a[mt][1], a[mt][2], a[mt][3], u0, u1);
                    }
                }
        }
        slot_c = slot_s;
    }

    // epilogue: SiLU(gate)*up -> act
    #pragma unroll
    for (int mt = 0; mt < 2; mt++) {
        const int r1 = m0 + wm + mt * 16 + g;
        const int r2 = r1 + 8;
        #pragma unroll
        for (int nt = 0; nt < 4; nt++) {
            const int col = n0 + wn + nt * 8 + 2 * tg;
            if (r1 < M) {
                float2 o;
                o.x = silu(cg[mt][nt][0]) * cu[mt][nt][0];
                o.y = silu(cg[mt][nt][1]) * cu[mt][nt][1];
                *(float2*)(act + (size_t)r1 * I_DIM + col) = o;
            }
            if (r2 < M) {
                float2 o;
                o.x = silu(cg[mt][nt][2]) * cu[mt][nt][2];
                o.y = silu(cg[mt][nt][3]) * cu[mt][nt][3];
                *(float2*)(act + (size_t)r2 * I_DIM + col) = o;
            }
        }
    }
}

// ============================================================================
// GEMM 2 (fp16, ldmatrix, 3-buffer ring): act @ Wd -> weighted atomicAdd out
// BM=128, BN=128, BK=16. SMEM slot: A[128*12], B[128*12] uints
// ============================================================================
#define G2_A  (128 * SA)
#define G2_B  (128 * SA)
#define G2_BUF (G2_A + G2_B)              // 3072 uints/slot
#define G2_SMEM (3 * G2_BUF * 4)          // 36864 B

__global__ __launch_bounds__(256, 2)
void mma_down_kernel(const float* __restrict__ Wd,
                     const float* __restrict__ Sd,
                     float* __restrict__ out) {
    extern __shared__ uint32_t smu[];
    const int e = blockIdx.z;
    const bool routed = (e < E_NUM);
    const int M = routed ? g_count[e] : T_TOK;
    const int m0 = blockIdx.y * 128;
    if (m0 >= M) return;
    const int n0 = blockIdx.x * 128;
    const float* W = routed ? (Wd + (size_t)e * I_DIM * H_DIM) : Sd;
    const int off = routed ? g_offset[e] : 0;
    const float* A = routed ? (g_act + (size_t)off * I_DIM) : g_act_sh;

    const int tid = threadIdx.x;
    const int lane = tid & 31, wid = tid >> 5;
    const int g = lane >> 2, tg = lane & 3;
    const int wm = (wid >> 1) * 32, wn = (wid & 1) * 64;
    const uint32_t smb = s2u(smu);

    const int arow_i = tid >> 1, cb = (tid & 1) * 8;
    int ar = m0 + arow_i;
    const float* Arow = A + (size_t)((ar < M) ? ar : m0) * I_DIM;
    const int bn = tid & 127, bkp = tid >> 7;
    const float* Bp = W + n0 + bn;

    const int lrow = lane & 15, lchunk = (lane >> 4) * 16;
    uint32_t aoff[2], boff[4];
    #pragma unroll
    for (int mt = 0; mt < 2; mt++)
        aoff[mt] = (uint32_t)((wm + mt * 16 + lrow) * SA * 4 + lchunk);
    #pragma unroll
    for (int p = 0; p < 4; p++)
        boff[p] = (uint32_t)(G2_A * 4 + (wn + p * 16 + lrow) * SA * 4 + lchunk);

    float cc[2][8][4];
    #pragma unroll
    for (int a = 0; a < 2; a++)
        #pragma unroll
        for (int b = 0; b < 8; b++)
            #pragma unroll
            for (int c = 0; c < 4; c++) cc[a][b][c] = 0.f;

    float4 pa0, pa1;
    float pb[8];
    const int NK = I_DIM / 16;    // 48
    const int abase = arow_i * SA + cb / 2;

    // prologue
    pa0 = *(const float4*)(Arow + cb);
    pa1 = *(const float4*)(Arow + cb + 4);
    #pragma unroll
    for (int j = 0; j < 4; j++) {
        int kp = bkp + 2 * j;
        pb[2 * j]     = Bp[(size_t)(2 * kp) * H_DIM];
        pb[2 * j + 1] = Bp[(size_t)(2 * kp + 1) * H_DIM];
    }
    {
        uint32_t* Ah = smu;
        uint32_t* Bh = Ah + G2_A;
        Ah[abase + 0] = pack2h(pa0.x, pa0.y);
        Ah[abase + 1] = pack2h(pa0.z, pa0.w);
        Ah[abase + 2] = pack2h(pa1.x, pa1.y);
        Ah[abase + 3] = pack2h(pa1.z, pa1.w);
        #pragma unroll
        for (int j = 0; j < 4; j++)
            Bh[bn * SA + bkp + 2 * j] = pack2h(pb[2 * j], pb[2 * j + 1]);
    }
    if (NK > 1) {
        const int k0 = 16;
        pa0 = *(const float4*)(Arow + k0 + cb);
        pa1 = *(const float4*)(Arow + k0 + cb + 4);
        #pragma unroll
        for (int j = 0; j < 4; j++) {
            int kp = bkp + 2 * j;
            pb[2 * j]     = Bp[(size_t)(k0 + 2 * kp) * H_DIM];
            pb[2 * j + 1] = Bp[(size_t)(k0 + 2 * kp + 1) * H_DIM];
        }
    }

    int slot_c = 0;
    for (int kt = 0; kt < NK; kt++) {
        __syncthreads();
        int slot_s = slot_c + 1; if (slot_s == 3) slot_s = 0;
        if (kt + 1 < NK) {
            uint32_t* Ah = smu + slot_s * G2_BUF;
            uint32_t* Bh = Ah + G2_A;
            Ah[abase + 0] = pack2h(pa0.x, pa0.y);
            Ah[abase + 1] = pack2h(pa0.z, pa0.w);
            Ah[abase + 2] = pack2h(pa1.x, pa1.y);
            Ah[abase + 3] = pack2h(pa1.z, pa1.w);
            #pragma unroll
            for (int j = 0; j < 4; j++)
                Bh[bn * SA + bkp + 2 * j] = pack2h(pb[2 * j], pb[2 * j + 1]);
        }
        if (kt + 2 < NK) {
            const int k0 = (kt + 2) * 16;
            pa0 = *(const float4*)(Arow + k0 + cb);
            pa1 = *(const float4*)(Arow + k0 + cb + 4);
            #pragma unroll
            for (int j = 0; j < 4; j++) {
                int kp = bkp + 2 * j;
                pb[2 * j]     = Bp[(size_t)(k0 + 2 * kp) * H_DIM];
                pb[2 * j + 1] = Bp[(size_t)(k0 + 2 * kp + 1) * H_DIM];
            }
        }
        {
            const uint32_t sb = smb + (uint32_t)(slot_c * G2_BUF * 4);
            uint32_t a[2][4], bb[4][4];
            #pragma unroll
            for (int mt = 0; mt < 2; mt++) ldm4(a[mt], sb + aoff[mt]);
            #pragma unroll
            for (int p = 0; p < 4; p++) ldm4(bb[p], sb + boff[p]);
            #pragma unroll
            for (int p = 0; p < 4; p++)
                #pragma unroll
                for (int s = 0; s < 2; s++) {
                    const int nt = p * 2 + s;
                    uint32_t b0 = bb[p][s], b1 = bb[p][s + 2];
                    #pragma unroll
                    for (int mt = 0; mt < 2; mt++)
                        mmah(cc[mt][nt], a[mt][0], a[mt][1], a[mt][2], a[mt][3], b0, b1);
                }
        }
        slot_c = slot_s;
    }

    // epilogue: weighted combine via atomics
    #pragma unroll
    for (int mt = 0; mt < 2; mt++) {
        const int r1 = m0 + wm + mt * 16 + g;
        const int r2 = r1 + 8;
        int tok1 = 0, tok2 = 0;
        float s1 = 0.f, s2 = 0.f;
        bool ok1 = (r1 < M), ok2 = (r2 < M);
        if (ok1) {
            if (routed) { tok1 = g_pair_token[off + r1]; s1 = g_pair_w[off + r1] * RSCALE; }
            else        { tok1 = r1; s1 = 1.0f; }
        }
        if (ok2) {
            if (routed) { tok2 = g_pair_token[off + r2]; s2 = g_pair_w[off + r2] * RSCALE; }
            else        { tok2 = r2; s2 = 1.0f; }
        }
        float* o1 = out + (size_t)tok1 * H_DIM;
        float* o2 = out + (size_t)tok2 * H_DIM;
        #pragma unroll
        for (int nt = 0; nt < 8; nt++) {
            const int col = n0 + wn + nt * 8 + 2 * tg;
            if (ok1) {
                atomicAdd(o1 + col,     cc[mt][nt][0] * s1);
                atomicAdd(o1 + col + 1, cc[mt][nt][1] * s1);
            }
            if (ok2) {
                atomicAdd(o2 + col,     cc[mt][nt][2] * s2);
                atomicAdd(o2 + col + 1, cc[mt][nt][3] * s2);
            }
        }
    }
}

// ---------------- launch ---------------------------------------------------
extern "C" void kernel_launch(void* const* d_in, const int* in_sizes, int n_in,
                              void* d_out, int out_size) {
    (void)in_sizes; (void)n_in; (void)out_size;
    const float* hidden    = (const float*)d_in[0];
    const float* gate_w    = (const float*)d_in[1];
    const float* gate_bias = (const float*)d_in[2];
    const float* w_gate_up = (const float*)d_in[3];
    const float* w_down    = (const float*)d_in[4];
    const float* s_gate_up = (const float*)d_in[5];
    const float* s_down    = (const float*)d_in[6];
    float* out = (float*)d_out;

    cudaFuncSetAttribute(mma_gateup_kernel, cudaFuncAttributeMaxDynamicSharedMemorySize, G1_SMEM);
    cudaFuncSetAttribute(mma_down_kernel,   cudaFuncAttributeMaxDynamicSharedMemorySize, G2_SMEM);

    init_kernel<<<1, 32>>>();
    routing_kernel<<<T_TOK, 256>>>(hidden, gate_w, gate_bias);
    scan_kernel<<<1, 32>>>();
    fill_kernel<<<(T_TOK * TOPK + 255) / 256, 256>>>();
    zero_out_kernel<<<(T_TOK * H_DIM / 4 + 255) / 256, 256>>>((float4*)out);

    {
        dim3 grid(I_DIM / 64, T_TOK / 128, E_NUM + 1);    // (12, 8, 33)
        mma_gateup_kernel<<<grid, 256, G1_SMEM>>>(hidden, w_gate_up, s_gate_up);
    }
    {
        dim3 grid(H_DIM / 128, T_TOK / 128, E_NUM + 1);   // (16, 8, 33)
        mma_down_kernel<<<grid, 256, G2_SMEM>>>(w_down, s_down, out);
    }
}

// round 13
// speedup vs baseline: 4.0854x; 1.0501x over previous
#include <cuda_runtime.h>
#include <cuda_fp16.h>
#include <math.h>
#include <stdint.h>

#define T_TOK 1024
#define H_DIM 2048
#define E_NUM 32
#define I_DIM 768
#define I2    1536
#define TOPK  8
#define NGROUP 4
#define GSIZE  8
#define TOPKG  2
#define RSCALE 2.5f
#define IH     (I_DIM / 2)   // act row length in uint (half2)
#define XH     (H_DIM / 2)   // xh row length in uint

// ---------------- scratch -------------------------------------------------
__device__ int   g_count[E_NUM];
__device__ int   g_offset[E_NUM];
__device__ int   g_cursor[E_NUM];
__device__ int   g_pair_token[T_TOK * TOPK];
__device__ float g_pair_w[T_TOK * TOPK];
__device__ int   g_tid_ids[T_TOK * TOPK];
__device__ float g_tid_w[T_TOK * TOPK];
__device__ uint32_t g_xh[(size_t)T_TOK * XH];            // hidden in fp16x2
__device__ uint32_t g_act[(size_t)T_TOK * TOPK * IH];    // routed act fp16x2
__device__ uint32_t g_act_sh[(size_t)T_TOK * IH];        // shared act fp16x2

// ---------------- helpers -------------------------------------------------
__device__ __forceinline__ uint32_t pack2h(float v0, float v1) {
    uint32_t r;
    asm("cvt.rn.f16x2.f32 %0, %1, %2;" : "=r"(r) : "f"(v1), "f"(v0));
    return r;
}
__device__ __forceinline__ uint32_t s2u(const void* p) {
    uint32_t a;
    asm("{ .reg .u64 t; cvta.to.shared.u64 t, %1; cvt.u32.u64 %0, t; }" : "=r"(a) : "l"(p));
    return a;
}
__device__ __forceinline__ void ldm4(uint32_t* d, uint32_t addr) {
    asm volatile("ldmatrix.sync.aligned.m8n8.x4.shared.b16 {%0,%1,%2,%3}, [%4];"
                 : "=r"(d[0]), "=r"(d[1]), "=r"(d[2]), "=r"(d[3]) : "r"(addr));
}
__device__ __forceinline__ void mmah(float* c,
                                     uint32_t a0, uint32_t a1, uint32_t a2, uint32_t a3,
                                     uint32_t b0, uint32_t b1) {
    asm volatile("mma.sync.aligned.m16n8k16.row.col.f32.f16.f16.f32 "
                 "{%0,%1,%2,%3}, {%4,%5,%6,%7}, {%8,%9}, {%0,%1,%2,%3};"
                 : "+f"(c[0]), "+f"(c[1]), "+f"(c[2]), "+f"(c[3])
                 : "r"(a0), "r"(a1), "r"(a2), "r"(a3), "r"(b0), "r"(b1));
}
__device__ __forceinline__ void red2(float* addr, float v0, float v1) {
    asm volatile("red.global.add.v2.f32 [%0], {%1, %2};"
                 :: "l"(addr), "f"(v0), "f"(v1) : "memory");
}
__device__ __forceinline__ float silu(float x) { return x / (1.f + expf(-x)); }

// ---------------- prep: zero out + init counters + X -> fp16 --------------
__global__ void prep_kernel(const float2* __restrict__ x, float4* __restrict__ out) {
    int idx = blockIdx.x * 256 + threadIdx.x;
    if (idx < T_TOK * XH) {
        float2 v = x[idx];
        g_xh[idx] = pack2h(v.x, v.y);
    }
    if (idx < T_TOK * H_DIM / 4) out[idx] = make_float4(0.f, 0.f, 0.f, 0.f);
    if (idx < E_NUM) { g_count[idx] = 0; g_cursor[idx] = 0; g_offset[idx] = 0; }
}

// ---------------- routing (proven) ----------------------------------------
__global__ void routing_kernel(const float* __restrict__ x,
                               const float* __restrict__ gw,
                               const float* __restrict__ gbias) {
    int t = blockIdx.x;
    __shared__ float xs[H_DIM];
    __shared__ float sc[E_NUM];
    __shared__ float scc[E_NUM];
    int tid = threadIdx.x;
    for (int h = tid; h < H_DIM; h += 256) xs[h] = x[(size_t)t * H_DIM + h];
    __syncthreads();
    int warp = tid >> 5, lane = tid & 31;
    for (int e = warp; e < E_NUM; e += 8) {
        const float* wrow = gw + (size_t)e * H_DIM;
        float s = 0.f;
        for (int h = lane; h < H_DIM; h += 32) s += xs[h] * wrow[h];
        #pragma unroll
        for (int o = 16; o > 0; o >>= 1) s += __shfl_xor_sync(0xffffffffu, s, o);
        if (lane == 0) {
            float sg = 1.f / (1.f + expf(-s));
            sc[e] = sg;
            scc[e] = sg + gbias[e];
        }
    }
    __syncthreads();
    if (tid == 0) {
        float gsc[NGROUP];
        #pragma unroll
        for (int g = 0; g < NGROUP; g++) {
            float m1 = -1e30f, m2 = -1e30f;
            for (int j = 0; j < GSIZE; j++) {
                float v = scc[g * GSIZE + j];
                if (v > m1) { m2 = m1; m1 = v; }
                else if (v > m2) { m2 = v; }
            }
            gsc[g] = m1 + m2;
        }
        bool gm[NGROUP] = {false, false, false, false};
        {
            float tg[NGROUP];
            #pragma unroll
            for (int g = 0; g < NGROUP; g++) tg[g] = gsc[g];
            for (int k = 0; k < TOPKG; k++) {
                int bi = 0; float bv = tg[0];
                for (int g = 1; g < NGROUP; g++) if (tg[g] > bv) { bv = tg[g]; bi = g; }
                gm[bi] = true; tg[bi] = -1e30f;
            }
        }
        float tmp[E_NUM];
        for (int e = 0; e < E_NUM; e++) tmp[e] = gm[e / GSIZE] ? scc[e] : 0.0f;
        int ids[TOPK]; float ws[TOPK]; float wsum = 0.f;
        for (int k = 0; k < TOPK; k++) {
            int bi = 0; float bv = tmp[0];
            for (int e = 1; e < E_NUM; e++) if (tmp[e] > bv) { bv = tmp[e]; bi = e; }
            ids[k] = bi; tmp[bi] = -1e30f;
            ws[k] = sc[bi]; wsum += ws[k];
        }
        float inv = 1.f / wsum;
        for (int k = 0; k < TOPK; k++) {
            g_tid_ids[t * TOPK + k] = ids[k];
            g_tid_w[t * TOPK + k] = ws[k] * inv;
            atomicAdd(&g_count[ids[k]], 1);
        }
    }
}

// ---------------- scan + fill (single block) -------------------------------
__global__ void scanfill_kernel() {
    int tid = threadIdx.x;
    if (tid == 0) {
        int acc = 0;
        for (int e = 0; e < E_NUM; e++) {
            g_offset[e] = acc; g_cursor[e] = acc; acc += g_count[e];
        }
    }
    __syncthreads();
    for (int i = tid; i < T_TOK * TOPK; i += 1024) {
        int e = g_tid_ids[i];
        int pos = atomicAdd(&g_cursor[e], 1);
        g_pair_token[pos] = i / TOPK;
        g_pair_w[pos]     = g_tid_w[i];
    }
}

// ============================================================================
// GEMM 1 (fp16, ldmatrix, 3-slot ring): Xh @ W[gate|up] -> act(fp16), SiLU*mul
// BM=128, BN=64(+64), BK=16. SMEM slot: A[128*12], Bg[64*12], Bu[64*12] uints
// ============================================================================
#define SA 12
#define G1_A  (128 * SA)
#define G1_B  (64 * SA)
#define G1_BUF (G1_A + 2 * G1_B)          // 3072 uints/slot
#define G1_SMEM (3 * G1_BUF * 4)          // 36864 B

__global__ __launch_bounds__(256, 2)
void mma_gateup_kernel(const float* __restrict__ Wgu,
                       const float* __restrict__ Sgu) {
    extern __shared__ uint32_t smu[];
    const int e = blockIdx.z;
    const bool routed = (e < E_NUM);
    const int M = routed ? g_count[e] : T_TOK;
    const int m0 = blockIdx.y * 128;
    if (m0 >= M) return;
    const int n0 = blockIdx.x * 64;
    const float* W = routed ? (Wgu + (size_t)e * H_DIM * I2) : Sgu;
    const int off = routed ? g_offset[e] : 0;
    uint32_t* act = routed ? (g_act + (size_t)off * IH) : g_act_sh;

    const int tid = threadIdx.x;
    const int lane = tid & 31, wid = tid >> 5;
    const int g = lane >> 2, tg = lane & 3;
    const int wm = (wid >> 1) * 32, wn = (wid & 1) * 32;
    const uint32_t smb = s2u(smu);

    const int arow_i = tid >> 1;
    const int au4 = tid & 1;                 // which uint4 of the k16 slab
    int ar = m0 + arow_i;
    int tokr = (ar < M) ? ar : m0;
    if (routed) tokr = g_pair_token[off + tokr];
    const uint4* Arow = (const uint4*)(g_xh + (size_t)tokr * XH);
    const int bn = tid & 63, bkp = tid >> 6;
    const float* Bgp = W + n0 + bn;
    const float* Bup = W + n0 + bn + I_DIM;

    const int lrow = lane & 15, lchunk = (lane >> 4) * 16;
    uint32_t aoff[2], bgoff[2], buoff[2];
    #pragma unroll
    for (int mt = 0; mt < 2; mt++)
        aoff[mt] = (uint32_t)((wm + mt * 16 + lrow) * SA * 4 + lchunk);
    #pragma unroll
    for (int p = 0; p < 2; p++) {
        bgoff[p] = (uint32_t)(G1_A * 4 + (wn + p * 16 + lrow) * SA * 4 + lchunk);
        buoff[p] = bgoff[p] + (uint32_t)(G1_B * 4);
    }

    float cg[2][4][4], cu[2][4][4];
    #pragma unroll
    for (int a = 0; a < 2; a++)
        #pragma unroll
        for (int b = 0; b < 4; b++)
            #pragma unroll
            for (int c = 0; c < 4; c++) { cg[a][b][c] = 0.f; cu[a][b][c] = 0.f; }

    uint4 pa;
    float pg[4], pu[4];
    const int NK = H_DIM / 16;   // 128
    const int abase = arow_i * SA + au4 * 4;
    const int bbase = bn * SA + bkp;

    // prologue: tile0 -> slot0; tile1 -> regs
    pa = Arow[au4];
    pg[0] = Bgp[(size_t)(2 * bkp) * I2];     pg[1] = Bgp[(size_t)(2 * bkp + 1) * I2];
    pg[2] = Bgp[(size_t)(2 * bkp + 8) * I2]; pg[3] = Bgp[(size_t)(2 * bkp + 9) * I2];
    pu[0] = Bup[(size_t)(2 * bkp) * I2];     pu[1] = Bup[(size_t)(2 * bkp + 1) * I2];
    pu[2] = Bup[(size_t)(2 * bkp + 8) * I2]; pu[3] = Bup[(size_t)(2 * bkp + 9) * I2];
    {
        uint32_t* Ah = smu;
        uint32_t* Bg = Ah + G1_A;
        uint32_t* Bu = Bg + G1_B;
        Ah[abase + 0] = pa.x; Ah[abase + 1] = pa.y;
        Ah[abase + 2] = pa.z; Ah[abase + 3] = pa.w;
        Bg[bbase]     = pack2h(pg[0], pg[1]);
        Bg[bbase + 4] = pack2h(pg[2], pg[3]);
        Bu[bbase]     = pack2h(pu[0], pu[1]);
        Bu[bbase + 4] = pack2h(pu[2], pu[3]);
    }
    if (NK > 1) {
        const int k0 = 16;
        pa = Arow[2 + au4];
        pg[0] = Bgp[(size_t)(k0 + 2 * bkp) * I2];     pg[1] = Bgp[(size_t)(k0 + 2 * bkp + 1) * I2];
        pg[2] = Bgp[(size_t)(k0 + 2 * bkp + 8) * I2]; pg[3] = Bgp[(size_t)(k0 + 2 * bkp + 9) * I2];
        pu[0] = Bup[(size_t)(k0 + 2 * bkp) * I2];     pu[1] = Bup[(size_t)(k0 + 2 * bkp + 1) * I2];
        pu[2] = Bup[(size_t)(k0 + 2 * bkp + 8) * I2]; pu[3] = Bup[(size_t)(k0 + 2 * bkp + 9) * I2];
    }

    int slot_c = 0;
    for (int kt = 0; kt < NK; kt++) {
        __syncthreads();
        int slot_s = slot_c + 1; if (slot_s == 3) slot_s = 0;
        if (kt + 1 < NK) {
            uint32_t* Ah = smu + slot_s * G1_BUF;
            uint32_t* Bg = Ah + G1_A;
            uint32_t* Bu = Bg + G1_B;
            Ah[abase + 0] = pa.x; Ah[abase + 1] = pa.y;
            Ah[abase + 2] = pa.z; Ah[abase + 3] = pa.w;
            Bg[bbase]     = pack2h(pg[0], pg[1]);
            Bg[bbase + 4] = pack2h(pg[2], pg[3]);
            Bu[bbase]     = pack2h(pu[0], pu[1]);
            Bu[bbase + 4] = pack2h(pu[2], pu[3]);
        }
        if (kt + 2 < NK) {
            const int k0 = (kt + 2) * 16;
            pa = Arow[(kt + 2) * 2 + au4];
            pg[0] = Bgp[(size_t)(k0 + 2 * bkp) * I2];     pg[1] = Bgp[(size_t)(k0 + 2 * bkp + 1) * I2];
            pg[2] = Bgp[(size_t)(k0 + 2 * bkp + 8) * I2]; pg[3] = Bgp[(size_t)(k0 + 2 * bkp + 9) * I2];
            pu[0] = Bup[(size_t)(k0 + 2 * bkp) * I2];     pu[1] = Bup[(size_t)(k0 + 2 * bkp + 1) * I2];
            pu[2] = Bup[(size_t)(k0 + 2 * bkp + 8) * I2]; pu[3] = Bup[(size_t)(k0 + 2 * bkp + 9) * I2];
        }
        {
            const uint32_t sb = smb + (uint32_t)(slot_c * G1_BUF * 4);
            uint32_t a[2][4], bg[2][4], bu[2][4];
            #pragma unroll
            for (int mt = 0; mt < 2; mt++) ldm4(a[mt], sb + aoff[mt]);
            #pragma unroll
            for (int p = 0; p < 2; p++) { ldm4(bg[p], sb + bgoff[p]); ldm4(bu[p], sb + buoff[p]); }
            #pragma unroll
            for (int p = 0; p < 2; p++)
                #pragma unroll
                for (int s = 0; s < 2; s++) {
                    const int nt = p * 2 + s;
                    uint32_t g0 = bg[p][s], g1 = bg[p][s + 2];
                    uint32_t u0 = bu[p][s], u1 = bu[p][s + 2];
                    #pragma unroll
                    for (int mt = 0; mt < 2; mt++) {
                        mmah(cg[mt][nt], a[mt][0], a[mt][1], a[mt][2], a[mt][3], g0, g1);
                        mmah(cu[mt][nt], a[mt][0], a[mt][1], a[mt][2], a[mt][3], u0, u1);
                    }
                }
        }
        slot_c = slot_s;
    }

    // epilogue: SiLU(gate)*up -> act (fp16x2 store)
    #pragma unroll
    for (int mt = 0; mt < 2; mt++) {
        const int r1 = m0 + wm + mt * 16 + g;
        const int r2 = r1 + 8;
        #pragma unroll
        for (int nt = 0; nt < 4; nt++) {
            const int col = n0 + wn + nt * 8 + 2 * tg;   // even
            if (r1 < M)
                act[(size_t)r1 * IH + col / 2] =
                    pack2h(silu(cg[mt][nt][0]) * cu[mt][nt][0],
                           silu(cg[mt][nt][1]) * cu[mt][nt][1]);
            if (r2 < M)
                act[(size_t)r2 * IH + col / 2] =
                    pack2h(silu(cg[mt][nt][2]) * cu[mt][nt][2],
                           silu(cg[mt][nt][3]) * cu[mt][nt][3]);
        }
    }
}

// ============================================================================
// GEMM 2 (fp16, ldmatrix, 3-slot ring): act(fp16) @ Wd -> v2-RED combine
// BM=128, BN=128, BK=16. SMEM slot: A[128*12], B[128*12] uints
// ============================================================================
#define G2_A  (128 * SA)
#define G2_B  (128 * SA)
#define G2_BUF (G2_A + G2_B)              // 3072 uints/slot
#define G2_SMEM (3 * G2_BUF * 4)          // 36864 B

__global__ __launch_bounds__(256, 2)
void mma_down_kernel(const float* __restrict__ Wd,
                     const float* __restrict__ Sd,
                     float* __restrict__ out) {
    extern __shared__ uint32_t smu[];
    const int e = blockIdx.z;
    const bool routed = (e < E_NUM);
    const int M = routed ? g_count[e] : T_TOK;
    const int m0 = blockIdx.y * 128;
    if (m0 >= M) return;
    const int n0 = blockIdx.x * 128;
    const float* W = routed ? (Wd + (size_t)e * I_DIM * H_DIM) : Sd;
    const int off = routed ? g_offset[e] : 0;
    const uint32_t* A = routed ? (g_act + (size_t)off * IH) : g_act_sh;

    const int tid = threadIdx.x;
    const int lane = tid & 31, wid = tid >> 5;
    const int g = lane >> 2, tg = lane & 3;
    const int wm = (wid >> 1) * 32, wn = (wid & 1) * 64;
    const uint32_t smb = s2u(smu);

    const int arow_i = tid >> 1;
    const int au4 = tid & 1;
    int ar = m0 + arow_i;
    const uint4* Arow = (const uint4*)(A + (size_t)((ar < M) ? ar : m0) * IH);
    const int bn = tid & 127, bkp = tid >> 7;
    const float* Bp = W + n0 + bn;

    const int lrow = lane & 15, lchunk = (lane >> 4) * 16;
    uint32_t aoff[2], boff[4];
    #pragma unroll
    for (int mt = 0; mt < 2; mt++)
        aoff[mt] = (uint32_t)((wm + mt * 16 + lrow) * SA * 4 + lchunk);
    #pragma unroll
    for (int p = 0; p < 4; p++)
        boff[p] = (uint32_t)(G2_A * 4 + (wn + p * 16 + lrow) * SA * 4 + lchunk);

    float cc[2][8][4];
    #pragma unroll
    for (int a = 0; a < 2; a++)
        #pragma unroll
        for (int b = 0; b < 8; b++)
            #pragma unroll
            for (int c = 0; c < 4; c++) cc[a][b][c] = 0.f;

    uint4 pa;
    float pb[8];
    const int NK = I_DIM / 16;    // 48
    const int abase = arow_i * SA + au4 * 4;

    pa = Arow[au4];
    #pragma unroll
    for (int j = 0; j < 4; j++) {
        int kp = bkp + 2 * j;
        pb[2 * j]     = Bp[(size_t)(2 * kp) * H_DIM];
        pb[2 * j + 1] = Bp[(size_t)(2 * kp + 1) * H_DIM];
    }
    {
        uint32_t* Ah = smu;
        uint32_t* Bh = Ah + G2_A;
        Ah[abase + 0] = pa.x; Ah[abase + 1] = pa.y;
        Ah[abase + 2] = pa.z; Ah[abase + 3] = pa.w;
        #pragma unroll
        for (int j = 0; j < 4; j++)
            Bh[bn * SA + bkp + 2 * j] = pack2h(pb[2 * j], pb[2 * j + 1]);
    }
    if (NK > 1) {
        const int k0 = 16;
        pa = Arow[2 + au4];
        #pragma unroll
        for (int j = 0; j < 4; j++) {
            int kp = bkp + 2 * j;
            pb[2 * j]     = Bp[(size_t)(k0 + 2 * kp) * H_DIM];
            pb[2 * j + 1] = Bp[(size_t)(k0 + 2 * kp + 1) * H_DIM];
        }
    }

    int slot_c = 0;
    for (int kt = 0; kt < NK; kt++) {
        __syncthreads();
        int slot_s = slot_c + 1; if (slot_s == 3) slot_s = 0;
        if (kt + 1 < NK) {
            uint32_t* Ah = smu + slot_s * G2_BUF;
            uint32_t* Bh = Ah + G2_A;
            Ah[abase + 0] = pa.x; Ah[abase + 1] = pa.y;
            Ah[abase + 2] = pa.z; Ah[abase + 3] = pa.w;
            #pragma unroll
            for (int j = 0; j < 4; j++)
                Bh[bn * SA + bkp + 2 * j] = pack2h(pb[2 * j], pb[2 * j + 1]);
        }
        if (kt + 2 < NK) {
            const int k0 = (kt + 2) * 16;
            pa = Arow[(kt + 2) * 2 + au4];
            #pragma unroll
            for (int j = 0; j < 4; j++) {
                int kp = bkp + 2 * j;
                pb[2 * j]     = Bp[(size_t)(k0 + 2 * kp) * H_DIM];
                pb[2 * j + 1] = Bp[(size_t)(k0 + 2 * kp + 1) * H_DIM];
            }
        }
        {
            const uint32_t sb = smb + (uint32_t)(slot_c * G2_BUF * 4);
            uint32_t a[2][4], bb[4][4];
            #pragma unroll
            for (int mt = 0; mt < 2; mt++) ldm4(a[mt], sb + aoff[mt]);
            #pragma unroll
            for (int p = 0; p < 4; p++) ldm4(bb[p], sb + boff[p]);
            #pragma unroll
            for (int p = 0; p < 4; p++)
                #pragma unroll
                for (int s = 0; s < 2; s++) {
                    const int nt = p * 2 + s;
                    uint32_t b0 = bb[p][s], b1 = bb[p][s + 2];
                    #pragma unroll
                    for (int mt = 0; mt < 2; mt++)
                        mmah(cc[mt][nt], a[mt][0], a[mt][1], a[mt][2], a[mt][3], b0, b1);
                }
        }
        slot_c = slot_s;
    }

    // epilogue: weighted combine via vector RED
    #pragma unroll
    for (int mt = 0; mt < 2; mt++) {
        const int r1 = m0 + wm + mt * 16 + g;
        const int r2 = r1 + 8;
        int tok1 = 0, tok2 = 0;
        float s1 = 0.f, s2 = 0.f;
        bool ok1 = (r1 < M), ok2 = (r2 < M);
        if (ok1) {
            if (routed) { tok1 = g_pair_token[off + r1]; s1 = g_pair_w[off + r1] * RSCALE; }
            else        { tok1 = r1; s1 = 1.0f; }
        }
        if (ok2) {
            if (routed) { tok2 = g_pair_token[off + r2]; s2 = g_pair_w[off + r2] * RSCALE; }
            else        { tok2 = r2; s2 = 1.0f; }
        }
        float* o1 = out + (size_t)tok1 * H_DIM;
        float* o2 = out + (size_t)tok2 * H_DIM;
        #pragma unroll
        for (int nt = 0; nt < 8; nt++) {
            const int col = n0 + wn + nt * 8 + 2 * tg;
            if (ok1) red2(o1 + col, cc[mt][nt][0] * s1, cc[mt][nt][1] * s1);
            if (ok2) red2(o2 + col, cc[mt][nt][2] * s2, cc[mt][nt][3] * s2);
        }
    }
}

// ---------------- launch ---------------------------------------------------
extern "C" void kernel_launch(void* const* d_in, const int* in_sizes, int n_in,
                              void* d_out, int out_size) {
    (void)in_sizes; (void)n_in; (void)out_size;
    const float* hidden    = (const float*)d_in[0];
    const float* gate_w    = (const float*)d_in[1];
    const float* gate_bias = (const float*)d_in[2];
    const float* w_gate_up = (const float*)d_in[3];
    const float* w_down    = (const float*)d_in[4];
    const float* s_gate_up = (const float*)d_in[5];
    const float* s_down    = (const float*)d_in[6];
    float* out = (float*)d_out;

    cudaFuncSetAttribute(mma_gateup_kernel, cudaFuncAttributeMaxDynamicSharedMemorySize, G1_SMEM);
    cudaFuncSetAttribute(mma_down_kernel,   cudaFuncAttributeMaxDynamicSharedMemorySize, G2_SMEM);

    prep_kernel<<<(T_TOK * XH + 255) / 256, 256>>>((const float2*)hidden, (float4*)out);
    routing_kernel<<<T_TOK, 256>>>(hidden, gate_w, gate_bias);
    scanfill_kernel<<<1, 1024>>>();

    {
        dim3 grid(I_DIM / 64, T_TOK / 128, E_NUM + 1);    // (12, 8, 33)
        mma_gateup_kernel<<<grid, 256, G1_SMEM>>>(w_gate_up, s_gate_up);
    }
    {
        dim3 grid(H_DIM / 128, T_TOK / 128, E_NUM + 1);   // (16, 8, 33)
        mma_down_kernel<<<grid, 256, G2_SMEM>>>(w_down, s_down, out);
    }
}

// round 14
// speedup vs baseline: 4.9301x; 1.2068x over previous
#include <cuda_runtime.h>
#include <cuda_fp16.h>
#include <math.h>
#include <stdint.h>

#define T_TOK 1024
#define H_DIM 2048
#define E_NUM 32
#define I_DIM 768
#define I2    1536
#define TOPK  8
#define NGROUP 4
#define GSIZE  8
#define TOPKG  2
#define RSCALE 2.5f
#define IH     (I_DIM / 2)
#define XH     (H_DIM / 2)

// ---------------- scratch -------------------------------------------------
__device__ int   g_count[E_NUM];
__device__ int   g_offset[E_NUM];
__device__ int   g_cursor[E_NUM];
__device__ int   g_pair_token[T_TOK * TOPK];
__device__ float g_pair_w[T_TOK * TOPK];
__device__ int   g_tid_ids[T_TOK * TOPK];
__device__ float g_tid_w[T_TOK * TOPK];
__device__ __align__(16) uint32_t g_xh[(size_t)T_TOK * XH];
__device__ __align__(16) uint32_t g_act[(size_t)T_TOK * TOPK * IH];
__device__ __align__(16) uint32_t g_act_sh[(size_t)T_TOK * IH];

// ---------------- helpers -------------------------------------------------
__device__ __forceinline__ uint32_t pack2h(float v0, float v1) {
    uint32_t r;
    asm("cvt.rn.f16x2.f32 %0, %1, %2;" : "=r"(r) : "f"(v1), "f"(v0));
    return r;
}
__device__ __forceinline__ uint32_t s2u(const void* p) {
    uint32_t a;
    asm("{ .reg .u64 t; cvta.to.shared.u64 t, %1; cvt.u32.u64 %0, t; }" : "=r"(a) : "l"(p));
    return a;
}
__device__ __forceinline__ void ldm4(uint32_t* d, uint32_t addr) {
    asm volatile("ldmatrix.sync.aligned.m8n8.x4.shared.b16 {%0,%1,%2,%3}, [%4];"
                 : "=r"(d[0]), "=r"(d[1]), "=r"(d[2]), "=r"(d[3]) : "r"(addr));
}
__device__ __forceinline__ void ldm4t(uint32_t* d, uint32_t addr) {
    asm volatile("ldmatrix.sync.aligned.m8n8.x4.trans.shared.b16 {%0,%1,%2,%3}, [%4];"
                 : "=r"(d[0]), "=r"(d[1]), "=r"(d[2]), "=r"(d[3]) : "r"(addr));
}
__device__ __forceinline__ void mmah(float* c,
                                     uint32_t a0, uint32_t a1, uint32_t a2, uint32_t a3,
                                     uint32_t b0, uint32_t b1) {
    asm volatile("mma.sync.aligned.m16n8k16.row.col.f32.f16.f16.f32 "
                 "{%0,%1,%2,%3}, {%4,%5,%6,%7}, {%8,%9}, {%0,%1,%2,%3};"
                 : "+f"(c[0]), "+f"(c[1]), "+f"(c[2]), "+f"(c[3])
                 : "r"(a0), "r"(a1), "r"(a2), "r"(a3), "r"(b0), "r"(b1));
}
__device__ __forceinline__ void red2(float* addr, float v0, float v1) {
    asm volatile("red.global.add.v2.f32 [%0], {%1, %2};"
                 :: "l"(addr), "f"(v0), "f"(v1) : "memory");
}
#define CPA16(dst, src) asm volatile("cp.async.cg.shared.global [%0], [%1], 16;" :: "r"(dst), "l"(src))
#define CPA_COMMIT()    asm volatile("cp.async.commit_group;" ::: "memory")
#define CPA_WAIT0()     asm volatile("cp.async.wait_group 0;" ::: "memory")
__device__ __forceinline__ float silu(float x) { return x / (1.f + expf(-x)); }

// ---------------- prep: zero out + init counters + X -> fp16 --------------
__global__ void prep_kernel(const float2* __restrict__ x, float4* __restrict__ out) {
    int idx = blockIdx.x * 256 + threadIdx.x;
    if (idx < T_TOK * XH) {
        float2 v = x[idx];
        g_xh[idx] = pack2h(v.x, v.y);
    }
    if (idx < T_TOK * H_DIM / 4) out[idx] = make_float4(0.f, 0.f, 0.f, 0.f);
    if (idx < E_NUM) { g_count[idx] = 0; g_cursor[idx] = 0; g_offset[idx] = 0; }
}

// ---------------- routing (proven) ----------------------------------------
__global__ void routing_kernel(const float* __restrict__ x,
                               const float* __restrict__ gw,
                               const float* __restrict__ gbias) {
    int t = blockIdx.x;
    __shared__ float xs[H_DIM];
    __shared__ float sc[E_NUM];
    __shared__ float scc[E_NUM];
    int tid = threadIdx.x;
    for (int h = tid; h < H_DIM; h += 256) xs[h] = x[(size_t)t * H_DIM + h];
    __syncthreads();
    int warp = tid >> 5, lane = tid & 31;
    for (int e = warp; e < E_NUM; e += 8) {
        const float* wrow = gw + (size_t)e * H_DIM;
        float s = 0.f;
        for (int h = lane; h < H_DIM; h += 32) s += xs[h] * wrow[h];
        #pragma unroll
        for (int o = 16; o > 0; o >>= 1) s += __shfl_xor_sync(0xffffffffu, s, o);
        if (lane == 0) {
            float sg = 1.f / (1.f + expf(-s));
            sc[e] = sg;
            scc[e] = sg + gbias[e];
        }
    }
    __syncthreads();
    if (tid == 0) {
        float gsc[NGROUP];
        #pragma unroll
        for (int g = 0; g < NGROUP; g++) {
            float m1 = -1e30f, m2 = -1e30f;
            for (int j = 0; j < GSIZE; j++) {
                float v = scc[g * GSIZE + j];
                if (v > m1) { m2 = m1; m1 = v; }
                else if (v > m2) { m2 = v; }
            }
            gsc[g] = m1 + m2;
        }
        bool gm[NGROUP] = {false, false, false, false};
        {
            float tg[NGROUP];
            #pragma unroll
            for (int g = 0; g < NGROUP; g++) tg[g] = gsc[g];
            for (int k = 0; k < TOPKG; k++) {
                int bi = 0; float bv = tg[0];
                for (int g = 1; g < NGROUP; g++) if (tg[g] > bv) { bv = tg[g]; bi = g; }
                gm[bi] = true; tg[bi] = -1e30f;
            }
        }
        float tmp[E_NUM];
        for (int e = 0; e < E_NUM; e++) tmp[e] = gm[e / GSIZE] ? scc[e] : 0.0f;
        int ids[TOPK]; float ws[TOPK]; float wsum = 0.f;
        for (int k = 0; k < TOPK; k++) {
            int bi = 0; float bv = tmp[0];
            for (int e = 1; e < E_NUM; e++) if (tmp[e] > bv) { bv = tmp[e]; bi = e; }
            ids[k] = bi; tmp[bi] = -1e30f;
            ws[k] = sc[bi]; wsum += ws[k];
        }
        float inv = 1.f / wsum;
        for (int k = 0; k < TOPK; k++) {
            g_tid_ids[t * TOPK + k] = ids[k];
            g_tid_w[t * TOPK + k] = ws[k] * inv;
            atomicAdd(&g_count[ids[k]], 1);
        }
    }
}

// ---------------- scan + fill (single block) -------------------------------
__global__ void scanfill_kernel() {
    int tid = threadIdx.x;
    if (tid == 0) {
        int acc = 0;
        for (int e = 0; e < E_NUM; e++) {
            g_offset[e] = acc; g_cursor[e] = acc; acc += g_count[e];
        }
    }
    __syncthreads();
    for (int i = tid; i < T_TOK * TOPK; i += 1024) {
        int e = g_tid_ids[i];
        int pos = atomicAdd(&g_cursor[e], 1);
        g_pair_token[pos] = i / TOPK;
        g_pair_w[pos]     = g_tid_w[i];
    }
}

// ============================================================================
// GEMM 1: Xh @ W[gate|up] -> act(fp16), SiLU*mul. BM=128, BN=64(+64), BK=32.
// SMEM slot: A[128 x 20u], Bg[32 x 36u], Bu[32 x 36u]. cp.async A, LDG.128 B.
// ============================================================================
#define SA1 20
#define SB1 36
#define A1_SZ (128 * SA1)                 // 2560 uints
#define B1_SZ (32 * SB1)                  // 1152 uints
#define SLOT1 (A1_SZ + 2 * B1_SZ)         // 4864 uints
#define G1_SMEM (3 * SLOT1 * 4)           // 58368 B

__global__ __launch_bounds__(256, 2)
void mma_gateup_kernel(const float* __restrict__ Wgu,
                       const float* __restrict__ Sgu) {
    extern __shared__ uint32_t smu[];
    const int e = blockIdx.z;
    const bool routed = (e < E_NUM);
    const int M = routed ? g_count[e] : T_TOK;
    const int m0 = blockIdx.y * 128;
    if (m0 >= M) return;
    const int n0 = blockIdx.x * 64;
    const float* W = routed ? (Wgu + (size_t)e * H_DIM * I2) : Sgu;
    const int off = routed ? g_offset[e] : 0;
    uint32_t* act = routed ? (g_act + (size_t)off * IH) : g_act_sh;

    const int tid = threadIdx.x;
    const int lane = tid & 31, wid = tid >> 5;
    const int g = lane >> 2, tg = lane & 3;
    const int wm = (wid >> 1) * 32, wn = (wid & 1) * 32;
    const uint32_t smb = s2u(smu);

    // A cp.async mapping
    const int arow_i = tid >> 1, au4 = tid & 1;
    int ar = m0 + arow_i;
    int tokr = (ar < M) ? ar : m0;
    if (routed) tokr = g_pair_token[off + tokr];
    const char* Asrc = (const char*)(g_xh + (size_t)tokr * XH);
    const uint32_t adst = (uint32_t)((arow_i * SA1 + au4 * 4) * 4);

    // B fill mapping: mat | 8 k-rows | 16 n4-groups
    const int bmat = tid >> 7;
    const int bt = tid & 127;
    const int bn4 = (bt & 15) * 4;
    const int bkr = bt >> 4;                       // 0..7
    const float* Bsrc = W + n0 + bmat * I_DIM;

    // ldmatrix offsets
    const int lrow = lane & 15, lchunk = (lane >> 4) * 16;
    const int brow_l = (lane & 7) + ((lane >> 3) & 1) * 8;
    const int jsel = lane >> 4;
    uint32_t aoff[2], bgoff[2];
    #pragma unroll
    for (int mt = 0; mt < 2; mt++)
        aoff[mt] = (uint32_t)((wm + mt * 16 + lrow) * SA1 * 4 + lchunk);
    #pragma unroll
    for (int p = 0; p < 2; p++)
        bgoff[p] = (uint32_t)(A1_SZ * 4 + brow_l * SB1 * 4 + ((wn >> 3) + 2 * p + jsel) * 16);

    float cg[2][4][4], cu[2][4][4];
    #pragma unroll
    for (int a = 0; a < 2; a++)
        #pragma unroll
        for (int b = 0; b < 4; b++)
            #pragma unroll
            for (int c = 0; c < 4; c++) { cg[a][b][c] = 0.f; cu[a][b][c] = 0.f; }

    float4 pb[4];
    const int NK = H_DIM / 32;   // 64

    // prologue: B(0)->regs->slot0, A(0) cp.async->slot0, B(1)->regs
    #pragma unroll
    for (int b = 0; b < 4; b++)
        pb[b] = *(const float4*)(Bsrc + (size_t)(bkr + 8 * b) * I2 + bn4);
    {
        uint32_t* Bq = smu + A1_SZ + bmat * B1_SZ;
        #pragma unroll
        for (int b = 0; b < 4; b++) {
            int row = bkr + 8 * b;
            uint2 v = make_uint2(pack2h(pb[b].x, pb[b].y), pack2h(pb[b].z, pb[b].w));
            *(uint2*)&Bq[row * SB1 + bn4 / 2] = v;
        }
        CPA16(smb + adst, Asrc + au4 * 16);
        CPA16(smb + adst + 32, Asrc + au4 * 16 + 32);
    }
    CPA_COMMIT();
    #pragma unroll
    for (int b = 0; b < 4; b++)
        pb[b] = *(const float4*)(Bsrc + (size_t)(32 + bkr + 8 * b) * I2 + bn4);

    int slot_c = 0;
    for (int kt = 0; kt < NK; kt++) {
        CPA_WAIT0();
        __syncthreads();
        int slot_s = slot_c + 1; if (slot_s == 3) slot_s = 0;
        if (kt + 1 < NK) {
            uint32_t* Bq = smu + slot_s * SLOT1 + A1_SZ + bmat * B1_SZ;
            #pragma unroll
            for (int b = 0; b < 4; b++) {
                int row = bkr + 8 * b;
                uint2 v = make_uint2(pack2h(pb[b].x, pb[b].y), pack2h(pb[b].z, pb[b].w));
                *(uint2*)&Bq[row * SB1 + bn4 / 2] = v;
            }
            uint32_t d0 = smb + (uint32_t)(slot_s * SLOT1 * 4) + adst;
            const char* s0 = Asrc + ((size_t)(kt + 1) * 4 + au4) * 16;
            CPA16(d0, s0);
            CPA16(d0 + 32, s0 + 32);
        }
        CPA_COMMIT();
        if (kt + 2 < NK) {
            const float* bp = Bsrc + (size_t)(kt + 2) * 32 * I2;
            #pragma unroll
            for (int b = 0; b < 4; b++)
                pb[b] = *(const float4*)(bp + (size_t)(bkr + 8 * b) * I2 + bn4);
        }
        {
            const uint32_t sb = smb + (uint32_t)(slot_c * SLOT1 * 4);
            #pragma unroll
            for (int kk = 0; kk < 2; kk++) {
                uint32_t a[2][4], bg[2][4], bu[2][4];
                #pragma unroll
                for (int mt = 0; mt < 2; mt++) ldm4(a[mt], sb + aoff[mt] + kk * 32);
                #pragma unroll
                for (int p = 0; p < 2; p++) {
                    ldm4t(bg[p], sb + bgoff[p] + kk * (16 * SB1 * 4));
                    ldm4t(bu[p], sb + bgoff[p] + B1_SZ * 4 + kk * (16 * SB1 * 4));
                }
                #pragma unroll
                for (int p = 0; p < 2; p++)
                    #pragma unroll
                    for (int s = 0; s < 2; s++) {
                        const int nt = p * 2 + s;
                        uint32_t g0 = bg[p][2 * s], g1 = bg[p][2 * s + 1];
                        uint32_t u0 = bu[p][2 * s], u1 = bu[p][2 * s + 1];
                        #pragma unroll
                        for (int mt = 0; mt < 2; mt++) {
                            mmah(cg[mt][nt], a[mt][0], a[mt][1], a[mt][2], a[mt][3], g0, g1);
                            mmah(cu[mt][nt], a[mt][0], a[mt][1], a[mt][2], a[mt][3], u0, u1);
                        }
                    }
            }
        }
        slot_c = slot_s;
    }

    // epilogue: SiLU(gate)*up -> act (fp16x2)
    #pragma unroll
    for (int mt = 0; mt < 2; mt++) {
        const int r1 = m0 + wm + mt * 16 + g;
        const int r2 = r1 + 8;
        #pragma unroll
        for (int nt = 0; nt < 4; nt++) {
            const int col = n0 + wn + nt * 8 + 2 * tg;
            if (r1 < M)
                act[(size_t)r1 * IH + col / 2] =
                    pack2h(silu(cg[mt][nt][0]) * cu[mt][nt][0],
                           silu(cg[mt][nt][1]) * cu[mt][nt][1]);
            if (r2 < M)
                act[(size_t)r2 * IH + col / 2] =
                    pack2h(silu(cg[mt][nt][2]) * cu[mt][nt][2],
                           silu(cg[mt][nt][3]) * cu[mt][nt][3]);
        }
    }
}

// ============================================================================
// GEMM 2: act(fp16) @ Wd -> v2-RED combine. BM=128, BN=128, BK=32.
// SMEM slot: A[128 x 20u], B[32 x 68u]. cp.async A, LDG.128 B, ldmatrix.trans.
// ============================================================================
#define SB2 68
#define A2_SZ (128 * SA1)                 // 2560
#define B2_SZ (32 * SB2)                  // 2176
#define SLOT2 (A2_SZ + B2_SZ)             // 4736
#define G2_SMEM (3 * SLOT2 * 4)           // 56832 B

__global__ __launch_bounds__(256, 2)
void mma_down_kernel(const float* __restrict__ Wd,
                     const float* __restrict__ Sd,
                     float* __restrict__ out) {
    extern __shared__ uint32_t smu[];
    const int e = blockIdx.z;
    const bool routed = (e < E_NUM);
    const int M = routed ? g_count[e] : T_TOK;
    const int m0 = blockIdx.y * 128;
    if (m0 >= M) return;
    const int n0 = blockIdx.x * 128;
    const float* W = routed ? (Wd + (size_t)e * I_DIM * H_DIM) : Sd;
    const int off = routed ? g_offset[e] : 0;
    const uint32_t* A = routed ? (g_act + (size_t)off * IH) : g_act_sh;

    const int tid = threadIdx.x;
    const int lane = tid & 31, wid = tid >> 5;
    const int g = lane >> 2, tg = lane & 3;
    const int wm = (wid >> 1) * 32, wn = (wid & 1) * 64;
    const uint32_t smb = s2u(smu);

    const int arow_i = tid >> 1, au4 = tid & 1;
    int ar = m0 + arow_i;
    const char* Asrc = (const char*)(A + (size_t)((ar < M) ? ar : m0) * IH);
    const uint32_t adst = (uint32_t)((arow_i * SA1 + au4 * 4) * 4);

    const int bn4 = (tid & 31) * 4;
    const int bkr = tid >> 5;                  // 0..7
    const float* Bsrc = W + n0;

    const int lrow = lane & 15, lchunk = (lane >> 4) * 16;
    const int brow_l = (lane & 7) + ((lane >> 3) & 1) * 8;
    const int jsel = lane >> 4;
    uint32_t aoff[2], boff[4];
    #pragma unroll
    for (int mt = 0; mt < 2; mt++)
        aoff[mt] = (uint32_t)((wm + mt * 16 + lrow) * SA1 * 4 + lchunk);
    #pragma unroll
    for (int p = 0; p < 4; p++)
        boff[p] = (uint32_t)(A2_SZ * 4 + brow_l * SB2 * 4 + ((wn >> 3) + 2 * p + jsel) * 16);

    float cc[2][8][4];
    #pragma unroll
    for (int a = 0; a < 2; a++)
        #pragma unroll
        for (int b = 0; b < 8; b++)
            #pragma unroll
            for (int c = 0; c < 4; c++) cc[a][b][c] = 0.f;

    float4 pb[4];
    const int NK = I_DIM / 32;    // 24

    #pragma unroll
    for (int b = 0; b < 4; b++)
        pb[b] = *(const float4*)(Bsrc + (size_t)(bkr + 8 * b) * H_DIM + bn4);
    {
        uint32_t* Bq = smu + A2_SZ;
        #pragma unroll
        for (int b = 0; b < 4; b++) {
            int row = bkr + 8 * b;
            uint2 v = make_uint2(pack2h(pb[b].x, pb[b].y), pack2h(pb[b].z, pb[b].w));
            *(uint2*)&Bq[row * SB2 + bn4 / 2] = v;
        }
        CPA16(smb + adst, Asrc + au4 * 16);
        CPA16(smb + adst + 32, Asrc + au4 * 16 + 32);
    }
    CPA_COMMIT();
    #pragma unroll
    for (int b = 0; b < 4; b++)
        pb[b] = *(const float4*)(Bsrc + (size_t)(32 + bkr + 8 * b) * H_DIM + bn4);

    int slot_c = 0;
    for (int kt = 0; kt < NK; kt++) {
        CPA_WAIT0();
        __syncthreads();
        int slot_s = slot_c + 1; if (slot_s == 3) slot_s = 0;
        if (kt + 1 < NK) {
            uint32_t* Bq = smu + slot_s * SLOT2 + A2_SZ;
            #pragma unroll
            for (int b = 0; b < 4; b++) {
                int row = bkr + 8 * b;
                uint2 v = make_uint2(pack2h(pb[b].x, pb[b].y), pack2h(pb[b].z, pb[b].w));
                *(uint2*)&Bq[row * SB2 + bn4 / 2] = v;
            }
            uint32_t d0 = smb + (uint32_t)(slot_s * SLOT2 * 4) + adst;
            const char* s0 = Asrc + ((size_t)(kt + 1) * 4 + au4) * 16;
            CPA16(d0, s0);
            CPA16(d0 + 32, s0 + 32);
        }
        CPA_COMMIT();
        if (kt + 2 < NK) {
            const float* bp = Bsrc + (size_t)(kt + 2) * 32 * H_DIM;
            #pragma unroll
            for (int b = 0; b < 4; b++)
                pb[b] = *(const float4*)(bp + (size_t)(bkr + 8 * b) * H_DIM + bn4);
        }
        {
            const uint32_t sb = smb + (uint32_t)(slot_c * SLOT2 * 4);
            #pragma unroll
            for (int kk = 0; kk < 2; kk++) {
                uint32_t a[2][4], bb[4][4];
                #pragma unroll
                for (int mt = 0; mt < 2; mt++) ldm4(a[mt], sb + aoff[mt] + kk * 32);
                #pragma unroll
                for (int p = 0; p < 4; p++) ldm4t(bb[p], sb + boff[p] + kk * (16 * SB2 * 4));
                #pragma unroll
                for (int p = 0; p < 4; p++)
                    #pragma unroll
                    for (int s = 0; s < 2; s++) {
                        const int nt = p * 2 + s;
                        uint32_t b0 = bb[p][2 * s], b1 = bb[p][2 * s + 1];
                        #pragma unroll
                        for (int mt = 0; mt < 2; mt++)
                            mmah(cc[mt][nt], a[mt][0], a[mt][1], a[mt][2], a[mt][3], b0, b1);
                    }
            }
        }
        slot_c = slot_s;
    }

    // epilogue: weighted combine via vector RED
    #pragma unroll
    for (int mt = 0; mt < 2; mt++) {
        const int r1 = m0 + wm + mt * 16 + g;
        const int r2 = r1 + 8;
        int tok1 = 0, tok2 = 0;
        float s1 = 0.f, s2 = 0.f;
        bool ok1 = (r1 < M), ok2 = (r2 < M);
        if (ok1) {
            if (routed) { tok1 = g_pair_token[off + r1]; s1 = g_pair_w[off + r1] * RSCALE; }
            else        { tok1 = r1; s1 = 1.0f; }
        }
        if (ok2) {
            if (routed) { tok2 = g_pair_token[off + r2]; s2 = g_pair_w[off + r2] * RSCALE; }
            else        { tok2 = r2; s2 = 1.0f; }
        }
        float* o1 = out + (size_t)tok1 * H_DIM;
        float* o2 = out + (size_t)tok2 * H_DIM;
        #pragma unroll
        for (int nt = 0; nt < 8; nt++) {
            const int col = n0 + wn + nt * 8 + 2 * tg;
            if (ok1) red2(o1 + col, cc[mt][nt][0] * s1, cc[mt][nt][1] * s1);
            if (ok2) red2(o2 + col, cc[mt][nt][2] * s2, cc[mt][nt][3] * s2);
        }
    }
}

// ---------------- launch ---------------------------------------------------
extern "C" void kernel_launch(void* const* d_in, const int* in_sizes, int n_in,
                              void* d_out, int out_size) {
    (void)in_sizes; (void)n_in; (void)out_size;
    const float* hidden    = (const float*)d_in[0];
    const float* gate_w    = (const float*)d_in[1];
    const float* gate_bias = (const float*)d_in[2];
    const float* w_gate_up = (const float*)d_in[3];
    const float* w_down    = (const float*)d_in[4];
    const float* s_gate_up = (const float*)d_in[5];
    const float* s_down    = (const float*)d_in[6];
    float* out = (float*)d_out;

    cudaFuncSetAttribute(mma_gateup_kernel, cudaFuncAttributeMaxDynamicSharedMemorySize, G1_SMEM);
    cudaFuncSetAttribute(mma_down_kernel,   cudaFuncAttributeMaxDynamicSharedMemorySize, G2_SMEM);

    prep_kernel<<<(T_TOK * XH + 255) / 256, 256>>>((const float2*)hidden, (float4*)out);
    routing_kernel<<<T_TOK, 256>>>(hidden, gate_w, gate_bias);
    scanfill_kernel<<<1, 1024>>>();

    {
        dim3 grid(I_DIM / 64, T_TOK / 128, E_NUM + 1);    // (12, 8, 33)
        mma_gateup_kernel<<<grid, 256, G1_SMEM>>>(w_gate_up, s_gate_up);
    }
    {
        dim3 grid(H_DIM / 128, T_TOK / 128, E_NUM + 1);   // (16, 8, 33)
        mma_down_kernel<<<grid, 256, G2_SMEM>>>(w_down, s_down, out);
    }
}